// round 12
// baseline (speedup 1.0000x reference)
#include <cuda_runtime.h>
#include <cuda_bf16.h>
#include <math.h>
#include <stdint.h>

// Problem constants
#define S_   1024
#define H_   2880
#define NH_  64
#define NKV_ 8
#define HD_  64
#define QKV_N_ 5120              // (NH + 2*NKV) * HD
#define KOFF_  4096              // NH*HD
#define VOFF_  4608              // NH*HD + NKV*HD
#define ATTN_N_ 4096             // NH*HD
#define SCALE_ 0.125f            // HD^-0.5

// ---------------------------------------------------------------------------
// Scratch (allocation-free: __device__ globals)
// ---------------------------------------------------------------------------
__device__ float g_qkv[S_ * QKV_N_];                    // 20 MB (pre-rope)
__device__ __nv_bfloat16 g_wqh[QKV_N_ * H_];            // qkv_w hi plane
__device__ __nv_bfloat16 g_wql[QKV_N_ * H_];            // qkv_w lo plane
__device__ __nv_bfloat16 g_woh[H_ * ATTN_N_];           // o_w hi
__device__ __nv_bfloat16 g_wol[H_ * ATTN_N_];           // o_w lo
__device__ __nv_bfloat16 g_xh[S_ * H_];                 // hidden hi
__device__ __nv_bfloat16 g_xl[S_ * H_];                 // hidden lo
__device__ __nv_bfloat16 g_qh[S_ * NH_ * HD_];          // roped Q hi
__device__ __nv_bfloat16 g_ql[S_ * NH_ * HD_];
__device__ __nv_bfloat16 g_kh[S_ * NKV_ * HD_];         // roped K hi
__device__ __nv_bfloat16 g_kl[S_ * NKV_ * HD_];
__device__ __nv_bfloat16 g_vth[NKV_ * HD_ * S_];        // V^T hi: [kv][d][s]
__device__ __nv_bfloat16 g_vtl[NKV_ * HD_ * S_];        // V^T lo
__device__ __nv_bfloat16 g_ah[S_ * ATTN_N_];            // attn out hi
__device__ __nv_bfloat16 g_al[S_ * ATTN_N_];

// ---------------------------------------------------------------------------
// Helpers
// ---------------------------------------------------------------------------
__device__ __forceinline__ void mma16816(float* c, const uint32_t* a, const uint32_t* b) {
    asm volatile(
        "mma.sync.aligned.m16n8k16.row.col.f32.bf16.bf16.f32 "
        "{%0,%1,%2,%3}, {%4,%5,%6,%7}, {%8,%9}, {%0,%1,%2,%3};\n"
        : "+f"(c[0]), "+f"(c[1]), "+f"(c[2]), "+f"(c[3])
        : "r"(a[0]), "r"(a[1]), "r"(a[2]), "r"(a[3]), "r"(b[0]), "r"(b[1]));
}

__device__ __forceinline__ void split2(float x, float y, uint32_t& hi, uint32_t& lo) {
    __nv_bfloat16 hx = __float2bfloat16(x);
    __nv_bfloat16 hy = __float2bfloat16(y);
    __nv_bfloat16 lx = __float2bfloat16(x - __bfloat162float(hx));
    __nv_bfloat16 ly = __float2bfloat16(y - __bfloat162float(hy));
    hi = ((uint32_t)__bfloat16_as_ushort(hy) << 16) | (uint32_t)__bfloat16_as_ushort(hx);
    lo = ((uint32_t)__bfloat16_as_ushort(ly) << 16) | (uint32_t)__bfloat16_as_ushort(lx);
}

__device__ __forceinline__ uint32_t smemu32(const void* p) {
    return (uint32_t)__cvta_generic_to_shared(p);
}

#define LDSM4(R0, R1, R2, R3, addr) \
    asm volatile("ldmatrix.sync.aligned.m8n8.x4.shared.b16 {%0,%1,%2,%3}, [%4];" \
                 : "=r"(R0), "=r"(R1), "=r"(R2), "=r"(R3) : "r"(addr))

#define CP16(dst, src) \
    asm volatile("cp.async.cg.shared.global [%0], [%1], 16;" :: "r"(dst), "l"(src))

// ---------------------------------------------------------------------------
// fp32 -> bf16 hi/lo plane split (vectorized)
// ---------------------------------------------------------------------------
__global__ __launch_bounds__(256)
void split_f32(const float* __restrict__ in, __nv_bfloat16* __restrict__ hi,
               __nv_bfloat16* __restrict__ lo, int n)
{
    int i = (blockIdx.x * 256 + threadIdx.x) * 4;
    if (i >= n) return;
    float4 v = *(const float4*)&in[i];
    uint32_t h0, l0, h1, l1;
    split2(v.x, v.y, h0, l0);
    split2(v.z, v.w, h1, l1);
    uint32_t* ph = (uint32_t*)&hi[i];
    uint32_t* pl = (uint32_t*)&lo[i];
    ph[0] = h0; ph[1] = h1;
    pl[0] = l0; pl[1] = l1;
}

// ---------------------------------------------------------------------------
// V transpose + split: g_qkv V section fp32 [s][kv][d] -> g_vt{h,l}[kv][d][s]
// Grid (S/32, NKV), block 256. smem tile transpose.
// ---------------------------------------------------------------------------
__global__ __launch_bounds__(256)
void vsplit_t()
{
    __shared__ float tile[32][65];
    const int s0 = blockIdx.x * 32;
    const int kv = blockIdx.y;
    const int tid = threadIdx.x;

    // load 32 s x 64 d, coalesced over d
    {
        const int sl = tid >> 3;          // 0..31
        const int dc = (tid & 7) * 8;     // 0,8,..,56
        const float* src = &g_qkv[(size_t)(s0 + sl) * QKV_N_ + VOFF_ + kv * HD_ + dc];
        float4 a = *(const float4*)&src[0];
        float4 b = *(const float4*)&src[4];
        tile[sl][dc + 0] = a.x; tile[sl][dc + 1] = a.y;
        tile[sl][dc + 2] = a.z; tile[sl][dc + 3] = a.w;
        tile[sl][dc + 4] = b.x; tile[sl][dc + 5] = b.y;
        tile[sl][dc + 6] = b.z; tile[sl][dc + 7] = b.w;
    }
    __syncthreads();

    // write transposed: each thread: one d row, 4 s-pairs
    {
        const int d  = tid >> 2;          // 0..63
        const int p0 = (tid & 3) * 4;     // s-pair base
        uint32_t* dh = (uint32_t*)&g_vth[((size_t)kv * HD_ + d) * S_ + s0];
        uint32_t* dl = (uint32_t*)&g_vtl[((size_t)kv * HD_ + d) * S_ + s0];
#pragma unroll
        for (int i = 0; i < 4; i++) {
            const int p = p0 + i;
            uint32_t hw, lw;
            split2(tile[2 * p][d], tile[2 * p + 1][d], hw, lw);
            dh[p] = hw;
            dl[p] = lw;
        }
    }
}

// ---------------------------------------------------------------------------
// Tensor-core GEMM (NT) on pre-split bf16 planes. 3-pass hi/lo, pass-outer
// MMA ordering (no same-accumulator back-to-back chains).
// ---------------------------------------------------------------------------
#define BM 128
#define BN 64
#define BK 32
#define ASTR 40
#define BUF_ELEMS (2 * BM * ASTR + 2 * BN * ASTR)

__global__ __launch_bounds__(256)
void gemm_planes(const __nv_bfloat16* __restrict__ Ah, const __nv_bfloat16* __restrict__ Al,
                 const __nv_bfloat16* __restrict__ Bh, const __nv_bfloat16* __restrict__ Bl,
                 float* __restrict__ C, int M, int N, int K)
{
    extern __shared__ __nv_bfloat16 sm[];

    const int tid  = threadIdx.x;
    const int wid  = tid >> 5;
    const int lane = tid & 31;
    const int g    = lane >> 2;
    const int cq   = lane & 3;
    const int wm   = (wid & 3) * 32;
    const int wn   = (wid >> 2) * 32;
    const int bm   = blockIdx.y * BM;
    const int bn   = blockIdx.x * BN;

    float acc[2][4][4];
#pragma unroll
    for (int mt = 0; mt < 2; mt++)
#pragma unroll
        for (int nt = 0; nt < 4; nt++)
#pragma unroll
            for (int i = 0; i < 4; i++) acc[mt][nt][i] = 0.f;

    const int ntile = K / BK;

    auto load_tile = [&](int t, int buf) {
        const int k0 = t * BK;
        __nv_bfloat16* s = sm + buf * BUF_ELEMS;
#pragma unroll
        for (int i = 0; i < 4; i++) {
            int c   = tid + i * 256;
            int p   = c >> 9;
            int r   = (c & 511) >> 2;
            int col = (c & 3) * 8;
            const __nv_bfloat16* src = (p ? Al : Ah) + (size_t)(bm + r) * K + k0 + col;
            CP16(smemu32(s + p * BM * ASTR + r * ASTR + col), src);
        }
#pragma unroll
        for (int i = 0; i < 2; i++) {
            int c   = tid + i * 256;
            int p   = c >> 8;
            int r   = (c & 255) >> 2;
            int col = (c & 3) * 8;
            const __nv_bfloat16* src = (p ? Bl : Bh) + (size_t)(bn + r) * K + k0 + col;
            CP16(smemu32(s + 2 * BM * ASTR + p * BN * ASTR + r * ASTR + col), src);
        }
        asm volatile("cp.async.commit_group;" ::);
    };

    load_tile(0, 0);

    const int lr  = lane & 15;
    const int hb  = (lane >> 4) * 8;
    const int l8  = lane & 7;
    const int sel = lane >> 3;

    for (int t = 0; t < ntile; t++) {
        asm volatile("cp.async.wait_group 0;" ::);
        __syncthreads();
        if (t + 1 < ntile) load_tile(t + 1, (t + 1) & 1);

        const __nv_bfloat16* s = sm + (t & 1) * BUF_ELEMS;
#pragma unroll
        for (int kk = 0; kk < 2; kk++) {
            uint32_t ah2[2][4], al2[2][4], bh2[2][4], bl2[2][4];
#pragma unroll
            for (int mt = 0; mt < 2; mt++) {
                uint32_t addr = smemu32(s + (wm + mt * 16 + lr) * ASTR + kk * 16 + hb);
                LDSM4(ah2[mt][0], ah2[mt][1], ah2[mt][2], ah2[mt][3], addr);
                addr = smemu32(s + BM * ASTR + (wm + mt * 16 + lr) * ASTR + kk * 16 + hb);
                LDSM4(al2[mt][0], al2[mt][1], al2[mt][2], al2[mt][3], addr);
            }
#pragma unroll
            for (int np = 0; np < 2; np++) {
                const int brow = wn + np * 16 + ((sel >> 1) << 3) + l8;
                const int bcol = kk * 16 + (sel & 1) * 8;
                LDSM4(bh2[np][0], bh2[np][1], bh2[np][2], bh2[np][3],
                      smemu32(s + 2 * BM * ASTR + brow * ASTR + bcol));
                LDSM4(bl2[np][0], bl2[np][1], bl2[np][2], bl2[np][3],
                      smemu32(s + 2 * BM * ASTR + BN * ASTR + brow * ASTR + bcol));
            }
            // pass 1: Ah * Bh  (8 independent accumulators)
#pragma unroll
            for (int mt = 0; mt < 2; mt++)
#pragma unroll
                for (int np = 0; np < 2; np++) {
                    mma16816(acc[mt][2 * np],     ah2[mt], &bh2[np][0]);
                    mma16816(acc[mt][2 * np + 1], ah2[mt], &bh2[np][2]);
                }
            // pass 2: Ah * Bl
#pragma unroll
            for (int mt = 0; mt < 2; mt++)
#pragma unroll
                for (int np = 0; np < 2; np++) {
                    mma16816(acc[mt][2 * np],     ah2[mt], &bl2[np][0]);
                    mma16816(acc[mt][2 * np + 1], ah2[mt], &bl2[np][2]);
                }
            // pass 3: Al * Bh
#pragma unroll
            for (int mt = 0; mt < 2; mt++)
#pragma unroll
                for (int np = 0; np < 2; np++) {
                    mma16816(acc[mt][2 * np],     al2[mt], &bh2[np][0]);
                    mma16816(acc[mt][2 * np + 1], al2[mt], &bh2[np][2]);
                }
        }
    }

#pragma unroll
    for (int mt = 0; mt < 2; mt++)
#pragma unroll
        for (int nt = 0; nt < 4; nt++) {
            int row = bm + wm + mt * 16 + g;
            int col = bn + wn + nt * 8 + cq * 2;
            *(float2*)&C[(size_t)row * N + col]       = make_float2(acc[mt][nt][0], acc[mt][nt][1]);
            *(float2*)&C[(size_t)(row + 8) * N + col] = make_float2(acc[mt][nt][2], acc[mt][nt][3]);
        }
}

// ---------------------------------------------------------------------------
// RoPE + split to bf16 planes. One 32-thread block per (s, q-or-k head).
// ---------------------------------------------------------------------------
__global__ void rope_split(const int* __restrict__ positions)
{
    const int row = blockIdx.x;
    const int s  = row / (NH_ + NKV_);
    const int hh = row % (NH_ + NKV_);
    const int i  = threadIdx.x;

    const float pos = (float)positions[s];
    const float inv_freq = powf(10000.0f, -(float)i / 32.0f);
    const float ang = pos * inv_freq;
    float c, sn;
    sincosf(ang, &sn, &c);

    const float* src;
    __nv_bfloat16 *dh, *dl;
    if (hh < NH_) {
        src = &g_qkv[(size_t)s * QKV_N_ + hh * HD_];
        dh = &g_qh[(size_t)s * (NH_ * HD_) + hh * HD_];
        dl = &g_ql[(size_t)s * (NH_ * HD_) + hh * HD_];
    } else {
        const int kvh = hh - NH_;
        src = &g_qkv[(size_t)s * QKV_N_ + KOFF_ + kvh * HD_];
        dh = &g_kh[(size_t)s * (NKV_ * HD_) + kvh * HD_];
        dl = &g_kl[(size_t)s * (NKV_ * HD_) + kvh * HD_];
    }
    const float x1 = src[i];
    const float x2 = src[i + 32];
    const float r1 = x1 * c - x2 * sn;
    const float r2 = x2 * c + x1 * sn;
    __nv_bfloat16 h1 = __float2bfloat16(r1);
    __nv_bfloat16 h2 = __float2bfloat16(r2);
    dh[i]      = h1;
    dh[i + 32] = h2;
    dl[i]      = __float2bfloat16(r1 - __bfloat162float(h1));
    dl[i + 32] = __float2bfloat16(r2 - __bfloat162float(h2));
}

// ---------------------------------------------------------------------------
// Flash attention (mma.sync, hi/lo 3-pass pass-outer), online softmax, sinks.
// All operands pre-split; staging is pure word copies.
// ---------------------------------------------------------------------------
#define VSTR 36

__global__ __launch_bounds__(128)
void flash_attn(const float* __restrict__ sinks)
{
    __shared__ uint32_t Qs[2][64 * VSTR];
    __shared__ uint32_t Ks[2][64 * VSTR];
    __shared__ uint32_t Vs[2][64 * VSTR];

    const int h   = blockIdx.y;
    const int qt  = (S_ / 64 - 1) - blockIdx.x;   // heavy tiles first
    const int q0  = qt * 64;
    const int kv  = h >> 3;
    const int tid = threadIdx.x;
    const int wid = tid >> 5;
    const int lane = tid & 31;
    const int g   = lane >> 2;
    const int cq  = lane & 3;
    const float sink = sinks[h];

    // ---- stage Q tile from planes ----
    {
        const int row = tid >> 1, e = tid & 1;
        const uint32_t* qh = (const uint32_t*)&g_qh[(size_t)(q0 + row) * (NH_ * HD_) + h * HD_ + e * 32];
        const uint32_t* ql = (const uint32_t*)&g_ql[(size_t)(q0 + row) * (NH_ * HD_) + h * HD_ + e * 32];
#pragma unroll
        for (int w = 0; w < 16; w++) {
            Qs[0][row * VSTR + e * 16 + w] = qh[w];
            Qs[1][row * VSTR + e * 16 + w] = ql[w];
        }
    }
    __syncthreads();

    uint32_t qa[2][4][4];
    {
        const int r0 = (wid * 16 + g) * VSTR;
        const int r8 = r0 + 8 * VSTR;
#pragma unroll
        for (int p = 0; p < 2; p++)
#pragma unroll
            for (int kt = 0; kt < 4; kt++) {
                const int w0 = kt * 8 + cq;
                qa[p][kt][0] = Qs[p][r0 + w0];
                qa[p][kt][1] = Qs[p][r8 + w0];
                qa[p][kt][2] = Qs[p][r0 + w0 + 4];
                qa[p][kt][3] = Qs[p][r8 + w0 + 4];
            }
    }

    float oacc[8][4];
#pragma unroll
    for (int nt = 0; nt < 8; nt++)
#pragma unroll
        for (int i = 0; i < 4; i++) oacc[nt][i] = 0.f;
    float m0 = -INFINITY, m8 = -INFINITY;
    float l0 = 0.f, l8 = 0.f;

    const int row_g  = q0 + wid * 16 + g;
    const int row_g8 = row_g + 8;
    const int ntiles = qt + 1;

    for (int t = 0; t < ntiles; t++) {
        const int k0 = t * 64;
        __syncthreads();

        // stage K tile from planes
        {
            const int key = tid >> 1, e = tid & 1;
            const uint32_t* kh = (const uint32_t*)&g_kh[(size_t)(k0 + key) * (NKV_ * HD_) + kv * HD_ + e * 32];
            const uint32_t* kl = (const uint32_t*)&g_kl[(size_t)(k0 + key) * (NKV_ * HD_) + kv * HD_ + e * 32];
#pragma unroll
            for (int w = 0; w < 16; w++) {
                Ks[0][key * VSTR + e * 16 + w] = kh[w];
                Ks[1][key * VSTR + e * 16 + w] = kl[w];
            }
        }
        // stage V^T tile from pre-transposed planes (pure copies)
        {
            const int d = tid >> 1, half = tid & 1;
            const uint32_t* vh = (const uint32_t*)&g_vth[((size_t)kv * HD_ + d) * S_ + k0];
            const uint32_t* vl = (const uint32_t*)&g_vtl[((size_t)kv * HD_ + d) * S_ + k0];
#pragma unroll
            for (int w = 0; w < 16; w++) {
                Vs[0][d * VSTR + half * 16 + w] = vh[half * 16 + w];
                Vs[1][d * VSTR + half * 16 + w] = vl[half * 16 + w];
            }
        }
        __syncthreads();

        // ---- S = Q K^T (pass-outer) ----
        float sacc[8][4];
#pragma unroll
        for (int nt = 0; nt < 8; nt++)
#pragma unroll
            for (int i = 0; i < 4; i++) sacc[nt][i] = 0.f;

#pragma unroll
        for (int kt = 0; kt < 4; kt++) {
            uint32_t kh[8][2], kl[8][2];
#pragma unroll
            for (int nt = 0; nt < 8; nt++) {
                const int r0 = (nt * 8 + g) * VSTR + kt * 8 + cq;
                kh[nt][0] = Ks[0][r0]; kh[nt][1] = Ks[0][r0 + 4];
                kl[nt][0] = Ks[1][r0]; kl[nt][1] = Ks[1][r0 + 4];
            }
#pragma unroll
            for (int nt = 0; nt < 8; nt++) mma16816(sacc[nt], qa[0][kt], kh[nt]);
#pragma unroll
            for (int nt = 0; nt < 8; nt++) mma16816(sacc[nt], qa[0][kt], kl[nt]);
#pragma unroll
            for (int nt = 0; nt < 8; nt++) mma16816(sacc[nt], qa[1][kt], kh[nt]);
        }

        // ---- scale + causal mask (last tile only) ----
        const bool last = (t == ntiles - 1);
#pragma unroll
        for (int nt = 0; nt < 8; nt++) {
            const int c0 = k0 + nt * 8 + 2 * cq;
#pragma unroll
            for (int i = 0; i < 4; i++) sacc[nt][i] *= SCALE_;
            if (last) {
                if (c0     > row_g)  sacc[nt][0] = -INFINITY;
                if (c0 + 1 > row_g)  sacc[nt][1] = -INFINITY;
                if (c0     > row_g8) sacc[nt][2] = -INFINITY;
                if (c0 + 1 > row_g8) sacc[nt][3] = -INFINITY;
            }
        }

        // ---- online softmax update ----
        float tm0 = -INFINITY, tm8 = -INFINITY;
#pragma unroll
        for (int nt = 0; nt < 8; nt++) {
            tm0 = fmaxf(tm0, fmaxf(sacc[nt][0], sacc[nt][1]));
            tm8 = fmaxf(tm8, fmaxf(sacc[nt][2], sacc[nt][3]));
        }
        tm0 = fmaxf(tm0, __shfl_xor_sync(0xffffffffu, tm0, 1));
        tm0 = fmaxf(tm0, __shfl_xor_sync(0xffffffffu, tm0, 2));
        tm8 = fmaxf(tm8, __shfl_xor_sync(0xffffffffu, tm8, 1));
        tm8 = fmaxf(tm8, __shfl_xor_sync(0xffffffffu, tm8, 2));

        const float m0n = fmaxf(m0, tm0);
        const float m8n = fmaxf(m8, tm8);
        const float a0 = __expf(m0 - m0n);
        const float a8 = __expf(m8 - m8n);
        m0 = m0n; m8 = m8n;
        l0 *= a0; l8 *= a8;
#pragma unroll
        for (int nt = 0; nt < 8; nt++) {
            oacc[nt][0] *= a0; oacc[nt][1] *= a0;
            oacc[nt][2] *= a8; oacc[nt][3] *= a8;
        }

#pragma unroll
        for (int nt = 0; nt < 8; nt++) {
            float p0 = (sacc[nt][0] == -INFINITY) ? 0.f : __expf(sacc[nt][0] - m0);
            float p1 = (sacc[nt][1] == -INFINITY) ? 0.f : __expf(sacc[nt][1] - m0);
            float p2 = (sacc[nt][2] == -INFINITY) ? 0.f : __expf(sacc[nt][2] - m8);
            float p3 = (sacc[nt][3] == -INFINITY) ? 0.f : __expf(sacc[nt][3] - m8);
            sacc[nt][0] = p0; sacc[nt][1] = p1; sacc[nt][2] = p2; sacc[nt][3] = p3;
            l0 += p0 + p1;
            l8 += p2 + p3;
        }

        // ---- O += P V (pass-outer) ----
#pragma unroll
        for (int kt = 0; kt < 4; kt++) {
            uint32_t pah[4], pal[4];
            split2(sacc[2 * kt][0],     sacc[2 * kt][1],     pah[0], pal[0]);
            split2(sacc[2 * kt][2],     sacc[2 * kt][3],     pah[1], pal[1]);
            split2(sacc[2 * kt + 1][0], sacc[2 * kt + 1][1], pah[2], pal[2]);
            split2(sacc[2 * kt + 1][2], sacc[2 * kt + 1][3], pah[3], pal[3]);
            uint32_t vh[8][2], vl[8][2];
#pragma unroll
            for (int nt = 0; nt < 8; nt++) {
                const int r0 = (nt * 8 + g) * VSTR + kt * 8 + cq;
                vh[nt][0] = Vs[0][r0]; vh[nt][1] = Vs[0][r0 + 4];
                vl[nt][0] = Vs[1][r0]; vl[nt][1] = Vs[1][r0 + 4];
            }
#pragma unroll
            for (int nt = 0; nt < 8; nt++) mma16816(oacc[nt], pah, vh[nt]);
#pragma unroll
            for (int nt = 0; nt < 8; nt++) mma16816(oacc[nt], pah, vl[nt]);
#pragma unroll
            for (int nt = 0; nt < 8; nt++) mma16816(oacc[nt], pal, vh[nt]);
        }
    }

    // ---- finalize with sink; write bf16 hi/lo planes ----
    {
        const float m0n = fmaxf(m0, sink);
        const float m8n = fmaxf(m8, sink);
        const float a0 = __expf(m0 - m0n);
        const float a8 = __expf(m8 - m8n);
        l0 *= a0; l8 *= a8;
        l0 += __shfl_xor_sync(0xffffffffu, l0, 1);
        l0 += __shfl_xor_sync(0xffffffffu, l0, 2);
        l8 += __shfl_xor_sync(0xffffffffu, l8, 1);
        l8 += __shfl_xor_sync(0xffffffffu, l8, 2);
        const float inv0 = a0 / (l0 + __expf(sink - m0n));
        const float inv8 = a8 / (l8 + __expf(sink - m8n));
#pragma unroll
        for (int nt = 0; nt < 8; nt++) {
            const int col = h * HD_ + nt * 8 + 2 * cq;
            uint32_t hw, lw;
            split2(oacc[nt][0] * inv0, oacc[nt][1] * inv0, hw, lw);
            *(uint32_t*)&g_ah[(size_t)row_g * ATTN_N_ + col] = hw;
            *(uint32_t*)&g_al[(size_t)row_g * ATTN_N_ + col] = lw;
            split2(oacc[nt][2] * inv8, oacc[nt][3] * inv8, hw, lw);
            *(uint32_t*)&g_ah[(size_t)row_g8 * ATTN_N_ + col] = hw;
            *(uint32_t*)&g_al[(size_t)row_g8 * ATTN_N_ + col] = lw;
        }
    }
}

// ---------------------------------------------------------------------------
// Launch
// ---------------------------------------------------------------------------
extern "C" void kernel_launch(void* const* d_in, const int* in_sizes, int n_in,
                              void* d_out, int out_size)
{
    const int*   positions = (const int*)d_in[0];
    const float* hidden    = (const float*)d_in[1];
    const float* qkv_w     = (const float*)d_in[2];
    const float* o_w       = (const float*)d_in[3];
    const float* sinks     = (const float*)d_in[4];
    float*       out       = (float*)d_out;

    static bool attr_done = false;
    if (!attr_done) {
        cudaFuncSetAttribute(gemm_planes, cudaFuncAttributeMaxDynamicSharedMemorySize,
                             2 * BUF_ELEMS * (int)sizeof(__nv_bfloat16));
        attr_done = true;
    }

    void *p;
    cudaGetSymbolAddress(&p, g_qkv);  float* qkv = (float*)p;
    cudaGetSymbolAddress(&p, g_wqh);  __nv_bfloat16* wqh = (__nv_bfloat16*)p;
    cudaGetSymbolAddress(&p, g_wql);  __nv_bfloat16* wql = (__nv_bfloat16*)p;
    cudaGetSymbolAddress(&p, g_woh);  __nv_bfloat16* woh = (__nv_bfloat16*)p;
    cudaGetSymbolAddress(&p, g_wol);  __nv_bfloat16* wol = (__nv_bfloat16*)p;
    cudaGetSymbolAddress(&p, g_xh);   __nv_bfloat16* xh  = (__nv_bfloat16*)p;
    cudaGetSymbolAddress(&p, g_xl);   __nv_bfloat16* xl  = (__nv_bfloat16*)p;
    cudaGetSymbolAddress(&p, g_ah);   __nv_bfloat16* ah  = (__nv_bfloat16*)p;
    cudaGetSymbolAddress(&p, g_al);   __nv_bfloat16* al  = (__nv_bfloat16*)p;

    const int smem = 2 * BUF_ELEMS * (int)sizeof(__nv_bfloat16);

    // 0) pre-split weights + activations to bf16 planes
    split_f32<<<(QKV_N_ * H_) / 1024, 256>>>(qkv_w, wqh, wql, QKV_N_ * H_);
    split_f32<<<(H_ * ATTN_N_) / 1024, 256>>>(o_w, woh, wol, H_ * ATTN_N_);
    split_f32<<<(S_ * H_) / 1024, 256>>>(hidden, xh, xl, S_ * H_);

    // 1) QKV projection: [1024,2880] @ [5120,2880]^T -> g_qkv fp32
    gemm_planes<<<dim3(QKV_N_ / BN, S_ / BM), 256, smem>>>(xh, xl, wqh, wql, qkv, S_, QKV_N_, H_);

    // 2) RoPE + split Q/K; transpose + split V
    rope_split<<<S_ * (NH_ + NKV_), 32>>>(positions);
    vsplit_t<<<dim3(S_ / 32, NKV_), 256>>>();

    // 3) Flash attention -> attn planes
    flash_attn<<<dim3(S_ / 64, NH_), 128>>>(sinks);

    // 4) O projection: attn planes @ o_w planes -> out fp32
    gemm_planes<<<dim3(H_ / BN, S_ / BM), 256, smem>>>(ah, al, woh, wol, out, S_, H_, ATTN_N_);
}

// round 13
// speedup vs baseline: 1.3143x; 1.3143x over previous
#include <cuda_runtime.h>
#include <cuda_bf16.h>
#include <cuda_fp16.h>
#include <math.h>
#include <stdint.h>

// Problem constants
#define S_   1024
#define H_   2880
#define NH_  64
#define NKV_ 8
#define HD_  64
#define QKV_N_ 5120              // (NH + 2*NKV) * HD
#define KOFF_  4096              // NH*HD
#define VOFF_  4608              // NH*HD + NKV*HD
#define ATTN_N_ 4096             // NH*HD
#define SCALE_ 0.125f            // HD^-0.5

// ---------------------------------------------------------------------------
// Scratch (allocation-free: __device__ globals). fp16 planes.
// Activations: 2-plane (exact to ~22 bits). Weights/V: single plane.
// ---------------------------------------------------------------------------
__device__ float g_qkv[S_ * QKV_N_];             // 20 MB (pre-rope)
__device__ __half g_wq[QKV_N_ * H_];             // qkv_w single fp16 plane
__device__ __half g_wo[H_ * ATTN_N_];            // o_w single fp16 plane
__device__ __half g_xh[S_ * H_];                 // hidden hi
__device__ __half g_xl[S_ * H_];                 // hidden lo
__device__ __half g_qh[S_ * NH_ * HD_];          // roped Q hi
__device__ __half g_ql[S_ * NH_ * HD_];
__device__ __half g_kh[S_ * NKV_ * HD_];         // roped K hi
__device__ __half g_kl[S_ * NKV_ * HD_];
__device__ __half g_vt[NKV_ * HD_ * S_];         // V^T single plane: [kv][d][s]
__device__ __half g_ah[S_ * ATTN_N_];            // attn out hi
__device__ __half g_al[S_ * ATTN_N_];

// ---------------------------------------------------------------------------
// Helpers
// ---------------------------------------------------------------------------
__device__ __forceinline__ void mma16816(float* c, const uint32_t* a, const uint32_t* b) {
    asm volatile(
        "mma.sync.aligned.m16n8k16.row.col.f32.f16.f16.f32 "
        "{%0,%1,%2,%3}, {%4,%5,%6,%7}, {%8,%9}, {%0,%1,%2,%3};\n"
        : "+f"(c[0]), "+f"(c[1]), "+f"(c[2]), "+f"(c[3])
        : "r"(a[0]), "r"(a[1]), "r"(a[2]), "r"(a[3]), "r"(b[0]), "r"(b[1]));
}

__device__ __forceinline__ void split2h(float x, float y, uint32_t& hi, uint32_t& lo) {
    __half hx = __float2half_rn(x);
    __half hy = __float2half_rn(y);
    __half lx = __float2half_rn(x - __half2float(hx));
    __half ly = __float2half_rn(y - __half2float(hy));
    hi = ((uint32_t)__half_as_ushort(hy) << 16) | (uint32_t)__half_as_ushort(hx);
    lo = ((uint32_t)__half_as_ushort(ly) << 16) | (uint32_t)__half_as_ushort(lx);
}

__device__ __forceinline__ uint32_t smemu32(const void* p) {
    return (uint32_t)__cvta_generic_to_shared(p);
}

#define LDSM4(R0, R1, R2, R3, addr) \
    asm volatile("ldmatrix.sync.aligned.m8n8.x4.shared.b16 {%0,%1,%2,%3}, [%4];" \
                 : "=r"(R0), "=r"(R1), "=r"(R2), "=r"(R3) : "r"(addr))

#define CP16(dst, src) \
    asm volatile("cp.async.cg.shared.global [%0], [%1], 16;" :: "r"(dst), "l"(src))

// ---------------------------------------------------------------------------
// fp32 -> fp16 hi/lo plane split (vectorized)
// ---------------------------------------------------------------------------
__global__ __launch_bounds__(256)
void split_f16(const float* __restrict__ in, __half* __restrict__ hi,
               __half* __restrict__ lo, int n)
{
    int i = (blockIdx.x * 256 + threadIdx.x) * 4;
    if (i >= n) return;
    float4 v = *(const float4*)&in[i];
    uint32_t h0, l0, h1, l1;
    split2h(v.x, v.y, h0, l0);
    split2h(v.z, v.w, h1, l1);
    uint32_t* ph = (uint32_t*)&hi[i];
    uint32_t* pl = (uint32_t*)&lo[i];
    ph[0] = h0; ph[1] = h1;
    pl[0] = l0; pl[1] = l1;
}

// fp32 -> single fp16 plane
__global__ __launch_bounds__(256)
void cvt_f16(const float* __restrict__ in, __half* __restrict__ out, int n)
{
    int i = (blockIdx.x * 256 + threadIdx.x) * 4;
    if (i >= n) return;
    float4 v = *(const float4*)&in[i];
    __half2* o = (__half2*)&out[i];
    o[0] = __floats2half2_rn(v.x, v.y);
    o[1] = __floats2half2_rn(v.z, v.w);
}

// ---------------------------------------------------------------------------
// V transpose + convert: g_qkv V section fp32 [s][kv][d] -> g_vt[kv][d][s] fp16
// ---------------------------------------------------------------------------
__global__ __launch_bounds__(256)
void vcvt_t()
{
    __shared__ float tile[32][65];
    const int s0 = blockIdx.x * 32;
    const int kv = blockIdx.y;
    const int tid = threadIdx.x;

    {
        const int sl = tid >> 3;
        const int dc = (tid & 7) * 8;
        const float* src = &g_qkv[(size_t)(s0 + sl) * QKV_N_ + VOFF_ + kv * HD_ + dc];
        float4 a = *(const float4*)&src[0];
        float4 b = *(const float4*)&src[4];
        tile[sl][dc + 0] = a.x; tile[sl][dc + 1] = a.y;
        tile[sl][dc + 2] = a.z; tile[sl][dc + 3] = a.w;
        tile[sl][dc + 4] = b.x; tile[sl][dc + 5] = b.y;
        tile[sl][dc + 6] = b.z; tile[sl][dc + 7] = b.w;
    }
    __syncthreads();

    {
        const int d  = tid >> 2;
        const int p0 = (tid & 3) * 4;
        __half2* dst = (__half2*)&g_vt[((size_t)kv * HD_ + d) * S_ + s0];
#pragma unroll
        for (int i = 0; i < 4; i++) {
            const int p = p0 + i;
            dst[p] = __floats2half2_rn(tile[2 * p][d], tile[2 * p + 1][d]);
        }
    }
}

// ---------------------------------------------------------------------------
// Tensor-core GEMM (NT): C[m,n] = sum_k A[m,k]*B[n,k]
// A = Ah + Al (2-plane fp16, exact), B = single fp16 plane. 2-pass, fp32 acc.
// BM=128, BN=64, BK=32, 256 threads.
// ---------------------------------------------------------------------------
#define BM 128
#define BN 64
#define BK 32
#define ASTR 40
#define GROWS (2 * BM + BN)                 // 320 rows per buffer
#define BUF_ELEMS (GROWS * ASTR)            // 12800 halves = 25600 B

__global__ __launch_bounds__(256)
void gemm_2p(const __half* __restrict__ Ah, const __half* __restrict__ Al,
             const __half* __restrict__ Bh,
             float* __restrict__ C, int M, int N, int K)
{
    extern __shared__ __half sm[];

    const int tid  = threadIdx.x;
    const int wid  = tid >> 5;
    const int lane = tid & 31;
    const int g    = lane >> 2;
    const int cq   = lane & 3;
    const int wm   = (wid & 3) * 32;
    const int wn   = (wid >> 2) * 32;
    const int bm   = blockIdx.y * BM;
    const int bn   = blockIdx.x * BN;

    float acc[2][4][4];
#pragma unroll
    for (int mt = 0; mt < 2; mt++)
#pragma unroll
        for (int nt = 0; nt < 4; nt++)
#pragma unroll
            for (int i = 0; i < 4; i++) acc[mt][nt][i] = 0.f;

    const int ntile = K / BK;

    // 5 x 16B chunks per thread per stage (320 rows x 4 chunks / 256 thr)
    auto load_tile = [&](int t, int buf) {
        const int k0 = t * BK;
        __half* s = sm + buf * BUF_ELEMS;
#pragma unroll
        for (int i = 0; i < 5; i++) {
            int c   = tid + i * 256;
            int r   = c >> 2;
            int col = (c & 3) * 8;
            const __half* src;
            if (r < BM)            src = Ah + (size_t)(bm + r) * K + k0 + col;
            else if (r < 2 * BM)   src = Al + (size_t)(bm + r - BM) * K + k0 + col;
            else                   src = Bh + (size_t)(bn + r - 2 * BM) * K + k0 + col;
            CP16(smemu32(s + r * ASTR + col), src);
        }
        asm volatile("cp.async.commit_group;" ::);
    };

    load_tile(0, 0);

    const int lr  = lane & 15;
    const int hb  = (lane >> 4) * 8;
    const int l8  = lane & 7;
    const int sel = lane >> 3;

    for (int t = 0; t < ntile; t++) {
        asm volatile("cp.async.wait_group 0;" ::);
        __syncthreads();
        if (t + 1 < ntile) load_tile(t + 1, (t + 1) & 1);

        const __half* s = sm + (t & 1) * BUF_ELEMS;
#pragma unroll
        for (int kk = 0; kk < 2; kk++) {
            uint32_t ah2[2][4], al2[2][4], bh2[2][4];
#pragma unroll
            for (int mt = 0; mt < 2; mt++) {
                uint32_t addr = smemu32(s + (wm + mt * 16 + lr) * ASTR + kk * 16 + hb);
                LDSM4(ah2[mt][0], ah2[mt][1], ah2[mt][2], ah2[mt][3], addr);
                addr = smemu32(s + BM * ASTR + (wm + mt * 16 + lr) * ASTR + kk * 16 + hb);
                LDSM4(al2[mt][0], al2[mt][1], al2[mt][2], al2[mt][3], addr);
            }
#pragma unroll
            for (int np = 0; np < 2; np++) {
                const int brow = wn + np * 16 + ((sel >> 1) << 3) + l8;
                const int bcol = kk * 16 + (sel & 1) * 8;
                LDSM4(bh2[np][0], bh2[np][1], bh2[np][2], bh2[np][3],
                      smemu32(s + 2 * BM * ASTR + brow * ASTR + bcol));
            }
            // pass 1: Ah * B
#pragma unroll
            for (int mt = 0; mt < 2; mt++)
#pragma unroll
                for (int np = 0; np < 2; np++) {
                    mma16816(acc[mt][2 * np],     ah2[mt], &bh2[np][0]);
                    mma16816(acc[mt][2 * np + 1], ah2[mt], &bh2[np][2]);
                }
            // pass 2: Al * B
#pragma unroll
            for (int mt = 0; mt < 2; mt++)
#pragma unroll
                for (int np = 0; np < 2; np++) {
                    mma16816(acc[mt][2 * np],     al2[mt], &bh2[np][0]);
                    mma16816(acc[mt][2 * np + 1], al2[mt], &bh2[np][2]);
                }
        }
    }

#pragma unroll
    for (int mt = 0; mt < 2; mt++)
#pragma unroll
        for (int nt = 0; nt < 4; nt++) {
            int row = bm + wm + mt * 16 + g;
            int col = bn + wn + nt * 8 + cq * 2;
            *(float2*)&C[(size_t)row * N + col]       = make_float2(acc[mt][nt][0], acc[mt][nt][1]);
            *(float2*)&C[(size_t)(row + 8) * N + col] = make_float2(acc[mt][nt][2], acc[mt][nt][3]);
        }
}

// ---------------------------------------------------------------------------
// RoPE + split to fp16 planes. One 32-thread block per (s, q-or-k head).
// ---------------------------------------------------------------------------
__global__ void rope_split(const int* __restrict__ positions)
{
    const int row = blockIdx.x;
    const int s  = row / (NH_ + NKV_);
    const int hh = row % (NH_ + NKV_);
    const int i  = threadIdx.x;

    const float pos = (float)positions[s];
    const float inv_freq = powf(10000.0f, -(float)i / 32.0f);
    const float ang = pos * inv_freq;
    float c, sn;
    sincosf(ang, &sn, &c);

    const float* src;
    __half *dh, *dl;
    if (hh < NH_) {
        src = &g_qkv[(size_t)s * QKV_N_ + hh * HD_];
        dh = &g_qh[(size_t)s * (NH_ * HD_) + hh * HD_];
        dl = &g_ql[(size_t)s * (NH_ * HD_) + hh * HD_];
    } else {
        const int kvh = hh - NH_;
        src = &g_qkv[(size_t)s * QKV_N_ + KOFF_ + kvh * HD_];
        dh = &g_kh[(size_t)s * (NKV_ * HD_) + kvh * HD_];
        dl = &g_kl[(size_t)s * (NKV_ * HD_) + kvh * HD_];
    }
    const float x1 = src[i];
    const float x2 = src[i + 32];
    const float r1 = x1 * c - x2 * sn;
    const float r2 = x2 * c + x1 * sn;
    __half h1 = __float2half_rn(r1);
    __half h2 = __float2half_rn(r2);
    dh[i]      = h1;
    dh[i + 32] = h2;
    dl[i]      = __float2half_rn(r1 - __half2float(h1));
    dl[i + 32] = __float2half_rn(r2 - __half2float(h2));
}

// ---------------------------------------------------------------------------
// Flash attention fp16: Q 2-plane, K 2-plane (3-pass QK^T), P 2-plane,
// V single plane (2-pass PV). Online softmax + sinks.
// ---------------------------------------------------------------------------
#define VSTR 36

__global__ __launch_bounds__(128)
void flash_attn(const float* __restrict__ sinks)
{
    __shared__ uint32_t Qs[2][64 * VSTR];
    __shared__ uint32_t Ks[2][64 * VSTR];
    __shared__ uint32_t Vs[64 * VSTR];

    const int h   = blockIdx.y;
    const int qt  = (S_ / 64 - 1) - blockIdx.x;   // heavy tiles first
    const int q0  = qt * 64;
    const int kv  = h >> 3;
    const int tid = threadIdx.x;
    const int wid = tid >> 5;
    const int lane = tid & 31;
    const int g   = lane >> 2;
    const int cq  = lane & 3;
    const float sink = sinks[h];

    // ---- stage Q tile from planes ----
    {
        const int row = tid >> 1, e = tid & 1;
        const uint32_t* qh = (const uint32_t*)&g_qh[(size_t)(q0 + row) * (NH_ * HD_) + h * HD_ + e * 32];
        const uint32_t* ql = (const uint32_t*)&g_ql[(size_t)(q0 + row) * (NH_ * HD_) + h * HD_ + e * 32];
#pragma unroll
        for (int w = 0; w < 16; w++) {
            Qs[0][row * VSTR + e * 16 + w] = qh[w];
            Qs[1][row * VSTR + e * 16 + w] = ql[w];
        }
    }
    __syncthreads();

    uint32_t qa[2][4][4];
    {
        const int r0 = (wid * 16 + g) * VSTR;
        const int r8 = r0 + 8 * VSTR;
#pragma unroll
        for (int p = 0; p < 2; p++)
#pragma unroll
            for (int kt = 0; kt < 4; kt++) {
                const int w0 = kt * 8 + cq;
                qa[p][kt][0] = Qs[p][r0 + w0];
                qa[p][kt][1] = Qs[p][r8 + w0];
                qa[p][kt][2] = Qs[p][r0 + w0 + 4];
                qa[p][kt][3] = Qs[p][r8 + w0 + 4];
            }
    }

    float oacc[8][4];
#pragma unroll
    for (int nt = 0; nt < 8; nt++)
#pragma unroll
        for (int i = 0; i < 4; i++) oacc[nt][i] = 0.f;
    float m0 = -INFINITY, m8 = -INFINITY;
    float l0 = 0.f, l8 = 0.f;

    const int row_g  = q0 + wid * 16 + g;
    const int row_g8 = row_g + 8;
    const int ntiles = qt + 1;

    for (int t = 0; t < ntiles; t++) {
        const int k0 = t * 64;
        __syncthreads();

        // stage K tile (2 planes)
        {
            const int key = tid >> 1, e = tid & 1;
            const uint32_t* kh = (const uint32_t*)&g_kh[(size_t)(k0 + key) * (NKV_ * HD_) + kv * HD_ + e * 32];
            const uint32_t* kl = (const uint32_t*)&g_kl[(size_t)(k0 + key) * (NKV_ * HD_) + kv * HD_ + e * 32];
#pragma unroll
            for (int w = 0; w < 16; w++) {
                Ks[0][key * VSTR + e * 16 + w] = kh[w];
                Ks[1][key * VSTR + e * 16 + w] = kl[w];
            }
        }
        // stage V^T tile (single plane, pure copies)
        {
            const int d = tid >> 1, half = tid & 1;
            const uint32_t* vh = (const uint32_t*)&g_vt[((size_t)kv * HD_ + d) * S_ + k0];
#pragma unroll
            for (int w = 0; w < 16; w++)
                Vs[d * VSTR + half * 16 + w] = vh[half * 16 + w];
        }
        __syncthreads();

        // ---- S = Q K^T (3-pass: qh*kh, qh*kl, ql*kh) ----
        float sacc[8][4];
#pragma unroll
        for (int nt = 0; nt < 8; nt++)
#pragma unroll
            for (int i = 0; i < 4; i++) sacc[nt][i] = 0.f;

#pragma unroll
        for (int kt = 0; kt < 4; kt++) {
            uint32_t kh[8][2], kl[8][2];
#pragma unroll
            for (int nt = 0; nt < 8; nt++) {
                const int r0 = (nt * 8 + g) * VSTR + kt * 8 + cq;
                kh[nt][0] = Ks[0][r0]; kh[nt][1] = Ks[0][r0 + 4];
                kl[nt][0] = Ks[1][r0]; kl[nt][1] = Ks[1][r0 + 4];
            }
#pragma unroll
            for (int nt = 0; nt < 8; nt++) mma16816(sacc[nt], qa[0][kt], kh[nt]);
#pragma unroll
            for (int nt = 0; nt < 8; nt++) mma16816(sacc[nt], qa[0][kt], kl[nt]);
#pragma unroll
            for (int nt = 0; nt < 8; nt++) mma16816(sacc[nt], qa[1][kt], kh[nt]);
        }

        // ---- scale + causal mask (last tile only) ----
        const bool last = (t == ntiles - 1);
#pragma unroll
        for (int nt = 0; nt < 8; nt++) {
            const int c0 = k0 + nt * 8 + 2 * cq;
#pragma unroll
            for (int i = 0; i < 4; i++) sacc[nt][i] *= SCALE_;
            if (last) {
                if (c0     > row_g)  sacc[nt][0] = -INFINITY;
                if (c0 + 1 > row_g)  sacc[nt][1] = -INFINITY;
                if (c0     > row_g8) sacc[nt][2] = -INFINITY;
                if (c0 + 1 > row_g8) sacc[nt][3] = -INFINITY;
            }
        }

        // ---- online softmax update ----
        float tm0 = -INFINITY, tm8 = -INFINITY;
#pragma unroll
        for (int nt = 0; nt < 8; nt++) {
            tm0 = fmaxf(tm0, fmaxf(sacc[nt][0], sacc[nt][1]));
            tm8 = fmaxf(tm8, fmaxf(sacc[nt][2], sacc[nt][3]));
        }
        tm0 = fmaxf(tm0, __shfl_xor_sync(0xffffffffu, tm0, 1));
        tm0 = fmaxf(tm0, __shfl_xor_sync(0xffffffffu, tm0, 2));
        tm8 = fmaxf(tm8, __shfl_xor_sync(0xffffffffu, tm8, 1));
        tm8 = fmaxf(tm8, __shfl_xor_sync(0xffffffffu, tm8, 2));

        const float m0n = fmaxf(m0, tm0);
        const float m8n = fmaxf(m8, tm8);
        const float a0 = __expf(m0 - m0n);
        const float a8 = __expf(m8 - m8n);
        m0 = m0n; m8 = m8n;
        l0 *= a0; l8 *= a8;
#pragma unroll
        for (int nt = 0; nt < 8; nt++) {
            oacc[nt][0] *= a0; oacc[nt][1] *= a0;
            oacc[nt][2] *= a8; oacc[nt][3] *= a8;
        }

#pragma unroll
        for (int nt = 0; nt < 8; nt++) {
            float p0 = (sacc[nt][0] == -INFINITY) ? 0.f : __expf(sacc[nt][0] - m0);
            float p1 = (sacc[nt][1] == -INFINITY) ? 0.f : __expf(sacc[nt][1] - m0);
            float p2 = (sacc[nt][2] == -INFINITY) ? 0.f : __expf(sacc[nt][2] - m8);
            float p3 = (sacc[nt][3] == -INFINITY) ? 0.f : __expf(sacc[nt][3] - m8);
            sacc[nt][0] = p0; sacc[nt][1] = p1; sacc[nt][2] = p2; sacc[nt][3] = p3;
            l0 += p0 + p1;
            l8 += p2 + p3;
        }

        // ---- O += P V (P 2-plane, V single: 2-pass) ----
#pragma unroll
        for (int kt = 0; kt < 4; kt++) {
            uint32_t pah[4], pal[4];
            split2h(sacc[2 * kt][0],     sacc[2 * kt][1],     pah[0], pal[0]);
            split2h(sacc[2 * kt][2],     sacc[2 * kt][3],     pah[1], pal[1]);
            split2h(sacc[2 * kt + 1][0], sacc[2 * kt + 1][1], pah[2], pal[2]);
            split2h(sacc[2 * kt + 1][2], sacc[2 * kt + 1][3], pah[3], pal[3]);
            uint32_t vh[8][2];
#pragma unroll
            for (int nt = 0; nt < 8; nt++) {
                const int r0 = (nt * 8 + g) * VSTR + kt * 8 + cq;
                vh[nt][0] = Vs[r0]; vh[nt][1] = Vs[r0 + 4];
            }
#pragma unroll
            for (int nt = 0; nt < 8; nt++) mma16816(oacc[nt], pah, vh[nt]);
#pragma unroll
            for (int nt = 0; nt < 8; nt++) mma16816(oacc[nt], pal, vh[nt]);
        }
    }

    // ---- finalize with sink; write fp16 hi/lo planes ----
    {
        const float m0n = fmaxf(m0, sink);
        const float m8n = fmaxf(m8, sink);
        const float a0 = __expf(m0 - m0n);
        const float a8 = __expf(m8 - m8n);
        l0 *= a0; l8 *= a8;
        l0 += __shfl_xor_sync(0xffffffffu, l0, 1);
        l0 += __shfl_xor_sync(0xffffffffu, l0, 2);
        l8 += __shfl_xor_sync(0xffffffffu, l8, 1);
        l8 += __shfl_xor_sync(0xffffffffu, l8, 2);
        const float inv0 = a0 / (l0 + __expf(sink - m0n));
        const float inv8 = a8 / (l8 + __expf(sink - m8n));
#pragma unroll
        for (int nt = 0; nt < 8; nt++) {
            const int col = h * HD_ + nt * 8 + 2 * cq;
            uint32_t hw, lw;
            split2h(oacc[nt][0] * inv0, oacc[nt][1] * inv0, hw, lw);
            *(uint32_t*)&g_ah[(size_t)row_g * ATTN_N_ + col] = hw;
            *(uint32_t*)&g_al[(size_t)row_g * ATTN_N_ + col] = lw;
            split2h(oacc[nt][2] * inv8, oacc[nt][3] * inv8, hw, lw);
            *(uint32_t*)&g_ah[(size_t)row_g8 * ATTN_N_ + col] = hw;
            *(uint32_t*)&g_al[(size_t)row_g8 * ATTN_N_ + col] = lw;
        }
    }
}

// ---------------------------------------------------------------------------
// Launch
// ---------------------------------------------------------------------------
extern "C" void kernel_launch(void* const* d_in, const int* in_sizes, int n_in,
                              void* d_out, int out_size)
{
    const int*   positions = (const int*)d_in[0];
    const float* hidden    = (const float*)d_in[1];
    const float* qkv_w     = (const float*)d_in[2];
    const float* o_w       = (const float*)d_in[3];
    const float* sinks     = (const float*)d_in[4];
    float*       out       = (float*)d_out;

    static bool attr_done = false;
    if (!attr_done) {
        cudaFuncSetAttribute(gemm_2p, cudaFuncAttributeMaxDynamicSharedMemorySize,
                             2 * BUF_ELEMS * (int)sizeof(__half));
        attr_done = true;
    }

    void *p;
    cudaGetSymbolAddress(&p, g_qkv);  float* qkv = (float*)p;
    cudaGetSymbolAddress(&p, g_wq);   __half* wq = (__half*)p;
    cudaGetSymbolAddress(&p, g_wo);   __half* wo = (__half*)p;
    cudaGetSymbolAddress(&p, g_xh);   __half* xh = (__half*)p;
    cudaGetSymbolAddress(&p, g_xl);   __half* xl = (__half*)p;
    cudaGetSymbolAddress(&p, g_ah);   __half* ah = (__half*)p;
    cudaGetSymbolAddress(&p, g_al);   __half* al = (__half*)p;

    const int smem = 2 * BUF_ELEMS * (int)sizeof(__half);

    // 0) pre-convert: weights single fp16 plane, hidden 2-plane fp16
    cvt_f16<<<(QKV_N_ * H_) / 1024, 256>>>(qkv_w, wq, QKV_N_ * H_);
    cvt_f16<<<(H_ * ATTN_N_) / 1024, 256>>>(o_w, wo, H_ * ATTN_N_);
    split_f16<<<(S_ * H_) / 1024, 256>>>(hidden, xh, xl, S_ * H_);

    // 1) QKV projection: [1024,2880] @ [5120,2880]^T -> g_qkv fp32
    gemm_2p<<<dim3(QKV_N_ / BN, S_ / BM), 256, smem>>>(xh, xl, wq, qkv, S_, QKV_N_, H_);

    // 2) RoPE + split Q/K; transpose + convert V
    rope_split<<<S_ * (NH_ + NKV_), 32>>>(positions);
    vcvt_t<<<dim3(S_ / 32, NKV_), 256>>>();

    // 3) Flash attention -> attn planes
    flash_attn<<<dim3(S_ / 64, NH_), 128>>>(sinks);

    // 4) O projection: attn planes @ o_w plane -> out fp32
    gemm_2p<<<dim3(H_ / BN, S_ / BM), 256, smem>>>(ah, al, wo, out, S_, H_, ATTN_N_);
}

// round 14
// speedup vs baseline: 1.4088x; 1.0719x over previous
#include <cuda_runtime.h>
#include <cuda_bf16.h>
#include <cuda_fp16.h>
#include <math.h>
#include <stdint.h>

// Problem constants
#define S_   1024
#define H_   2880
#define NH_  64
#define NKV_ 8
#define HD_  64
#define QKV_N_ 5120              // (NH + 2*NKV) * HD
#define KOFF_  4096              // NH*HD
#define VOFF_  4608              // NH*HD + NKV*HD
#define ATTN_N_ 4096             // NH*HD
#define SCALE_ 0.125f            // HD^-0.5

// ---------------------------------------------------------------------------
// Scratch (allocation-free: __device__ globals). fp16 planes.
// ---------------------------------------------------------------------------
__device__ float g_qkv[S_ * QKV_N_];             // 20 MB (pre-rope)
__device__ __half g_wq[QKV_N_ * H_];             // qkv_w single fp16 plane
__device__ __half g_wo[H_ * ATTN_N_];            // o_w single fp16 plane
__device__ __half g_xh[S_ * H_];                 // hidden hi
__device__ __half g_xl[S_ * H_];                 // hidden lo
__device__ __half g_qh[S_ * NH_ * HD_];          // roped Q hi
__device__ __half g_ql[S_ * NH_ * HD_];
__device__ __half g_kh[S_ * NKV_ * HD_];         // roped K hi
__device__ __half g_kl[S_ * NKV_ * HD_];
__device__ __half g_vt[NKV_ * HD_ * S_];         // V^T single plane: [kv][d][s]
__device__ __half g_ah[S_ * ATTN_N_];            // attn out hi
__device__ __half g_al[S_ * ATTN_N_];

// ---------------------------------------------------------------------------
// Helpers
// ---------------------------------------------------------------------------
__device__ __forceinline__ void mma16816(float* c, const uint32_t* a, const uint32_t* b) {
    asm volatile(
        "mma.sync.aligned.m16n8k16.row.col.f32.f16.f16.f32 "
        "{%0,%1,%2,%3}, {%4,%5,%6,%7}, {%8,%9}, {%0,%1,%2,%3};\n"
        : "+f"(c[0]), "+f"(c[1]), "+f"(c[2]), "+f"(c[3])
        : "r"(a[0]), "r"(a[1]), "r"(a[2]), "r"(a[3]), "r"(b[0]), "r"(b[1]));
}

__device__ __forceinline__ void split2h(float x, float y, uint32_t& hi, uint32_t& lo) {
    __half hx = __float2half_rn(x);
    __half hy = __float2half_rn(y);
    __half lx = __float2half_rn(x - __half2float(hx));
    __half ly = __float2half_rn(y - __half2float(hy));
    hi = ((uint32_t)__half_as_ushort(hy) << 16) | (uint32_t)__half_as_ushort(hx);
    lo = ((uint32_t)__half_as_ushort(ly) << 16) | (uint32_t)__half_as_ushort(lx);
}

__device__ __forceinline__ uint32_t smemu32(const void* p) {
    return (uint32_t)__cvta_generic_to_shared(p);
}

#define LDSM4(R0, R1, R2, R3, addr) \
    asm volatile("ldmatrix.sync.aligned.m8n8.x4.shared.b16 {%0,%1,%2,%3}, [%4];" \
                 : "=r"(R0), "=r"(R1), "=r"(R2), "=r"(R3) : "r"(addr))

#define CP16(dst, src) \
    asm volatile("cp.async.cg.shared.global [%0], [%1], 16;" :: "r"(dst), "l"(src))

// ---------------------------------------------------------------------------
// fp32 -> fp16 hi/lo plane split (vectorized)
// ---------------------------------------------------------------------------
__global__ __launch_bounds__(256)
void split_f16(const float* __restrict__ in, __half* __restrict__ hi,
               __half* __restrict__ lo, int n)
{
    int i = (blockIdx.x * 256 + threadIdx.x) * 4;
    if (i >= n) return;
    float4 v = *(const float4*)&in[i];
    uint32_t h0, l0, h1, l1;
    split2h(v.x, v.y, h0, l0);
    split2h(v.z, v.w, h1, l1);
    uint32_t* ph = (uint32_t*)&hi[i];
    uint32_t* pl = (uint32_t*)&lo[i];
    ph[0] = h0; ph[1] = h1;
    pl[0] = l0; pl[1] = l1;
}

// fp32 -> single fp16 plane
__global__ __launch_bounds__(256)
void cvt_f16(const float* __restrict__ in, __half* __restrict__ out, int n)
{
    int i = (blockIdx.x * 256 + threadIdx.x) * 4;
    if (i >= n) return;
    float4 v = *(const float4*)&in[i];
    __half2* o = (__half2*)&out[i];
    o[0] = __floats2half2_rn(v.x, v.y);
    o[1] = __floats2half2_rn(v.z, v.w);
}

// ---------------------------------------------------------------------------
// V transpose + convert: g_qkv V section fp32 [s][kv][d] -> g_vt[kv][d][s] fp16
// ---------------------------------------------------------------------------
__global__ __launch_bounds__(256)
void vcvt_t()
{
    __shared__ float tile[32][65];
    const int s0 = blockIdx.x * 32;
    const int kv = blockIdx.y;
    const int tid = threadIdx.x;

    {
        const int sl = tid >> 3;
        const int dc = (tid & 7) * 8;
        const float* src = &g_qkv[(size_t)(s0 + sl) * QKV_N_ + VOFF_ + kv * HD_ + dc];
        float4 a = *(const float4*)&src[0];
        float4 b = *(const float4*)&src[4];
        tile[sl][dc + 0] = a.x; tile[sl][dc + 1] = a.y;
        tile[sl][dc + 2] = a.z; tile[sl][dc + 3] = a.w;
        tile[sl][dc + 4] = b.x; tile[sl][dc + 5] = b.y;
        tile[sl][dc + 6] = b.z; tile[sl][dc + 7] = b.w;
    }
    __syncthreads();

    {
        const int d  = tid >> 2;
        const int p0 = (tid & 3) * 4;
        __half2* dst = (__half2*)&g_vt[((size_t)kv * HD_ + d) * S_ + s0];
#pragma unroll
        for (int i = 0; i < 4; i++) {
            const int p = p0 + i;
            dst[p] = __floats2half2_rn(tile[2 * p][d], tile[2 * p + 1][d]);
        }
    }
}

// ---------------------------------------------------------------------------
// Tensor-core GEMM (NT): C[m,n] = sum_k A[m,k]*B[n,k]
// A = Ah + Al (2-plane fp16), B = single fp16 plane. 2-pass, fp32 acc.
// BM=128, BN_ templated (128 / 96), BK=32, 256 threads, warp tile 32 x BN_/2.
// ---------------------------------------------------------------------------
#define BM 128
#define BK 32
#define ASTR 40

template<int BN_>
__global__ __launch_bounds__(256)
void gemm_2p(const __half* __restrict__ Ah, const __half* __restrict__ Al,
             const __half* __restrict__ Bp,
             float* __restrict__ C, int M, int N, int K)
{
    constexpr int NP   = BN_ / 32;              // 16-col LDSM chunks per warp
    constexpr int GR   = 2 * BM + BN_;          // rows per buffer
    constexpr int BUFE = GR * ASTR;             // halves per buffer
    constexpr int NCH  = (GR * 4 + 255) / 256;  // 16B chunks per thread per stage

    extern __shared__ __half sm[];

    const int tid  = threadIdx.x;
    const int wid  = tid >> 5;
    const int lane = tid & 31;
    const int g    = lane >> 2;
    const int cq   = lane & 3;
    const int wm   = (wid & 3) * 32;
    const int wn   = (wid >> 2) * (BN_ / 2);
    const int bm   = blockIdx.y * BM;
    const int bn   = blockIdx.x * BN_;

    float acc[2][2 * NP][4];
#pragma unroll
    for (int mt = 0; mt < 2; mt++)
#pragma unroll
        for (int nt = 0; nt < 2 * NP; nt++)
#pragma unroll
            for (int i = 0; i < 4; i++) acc[mt][nt][i] = 0.f;

    const int ntile = K / BK;

    auto load_tile = [&](int t, int buf) {
        const int k0 = t * BK;
        __half* s = sm + buf * BUFE;
#pragma unroll
        for (int i = 0; i < NCH; i++) {
            int c = tid + i * 256;
            if (c < GR * 4) {
                int r = c >> 2, col = (c & 3) * 8;
                const __half* src;
                if (r < BM)            src = Ah + (size_t)(bm + r) * K + k0 + col;
                else if (r < 2 * BM)   src = Al + (size_t)(bm + r - BM) * K + k0 + col;
                else                   src = Bp + (size_t)(bn + r - 2 * BM) * K + k0 + col;
                CP16(smemu32(s + r * ASTR + col), src);
            }
        }
        asm volatile("cp.async.commit_group;" ::);
    };

    load_tile(0, 0);

    const int lr  = lane & 15;
    const int hb  = (lane >> 4) * 8;
    const int l8  = lane & 7;
    const int sel = lane >> 3;

    for (int t = 0; t < ntile; t++) {
        asm volatile("cp.async.wait_group 0;" ::);
        __syncthreads();
        if (t + 1 < ntile) load_tile(t + 1, (t + 1) & 1);

        const __half* s = sm + (t & 1) * BUFE;
#pragma unroll
        for (int kk = 0; kk < 2; kk++) {
            uint32_t ah2[2][4], al2[2][4], bh2[NP][4];
#pragma unroll
            for (int mt = 0; mt < 2; mt++) {
                uint32_t addr = smemu32(s + (wm + mt * 16 + lr) * ASTR + kk * 16 + hb);
                LDSM4(ah2[mt][0], ah2[mt][1], ah2[mt][2], ah2[mt][3], addr);
                addr = smemu32(s + BM * ASTR + (wm + mt * 16 + lr) * ASTR + kk * 16 + hb);
                LDSM4(al2[mt][0], al2[mt][1], al2[mt][2], al2[mt][3], addr);
            }
#pragma unroll
            for (int np = 0; np < NP; np++) {
                const int brow = wn + np * 16 + ((sel >> 1) << 3) + l8;
                const int bcol = kk * 16 + (sel & 1) * 8;
                LDSM4(bh2[np][0], bh2[np][1], bh2[np][2], bh2[np][3],
                      smemu32(s + 2 * BM * ASTR + brow * ASTR + bcol));
            }
            // pass 1: Ah * B
#pragma unroll
            for (int mt = 0; mt < 2; mt++)
#pragma unroll
                for (int np = 0; np < NP; np++) {
                    mma16816(acc[mt][2 * np],     ah2[mt], &bh2[np][0]);
                    mma16816(acc[mt][2 * np + 1], ah2[mt], &bh2[np][2]);
                }
            // pass 2: Al * B
#pragma unroll
            for (int mt = 0; mt < 2; mt++)
#pragma unroll
                for (int np = 0; np < NP; np++) {
                    mma16816(acc[mt][2 * np],     al2[mt], &bh2[np][0]);
                    mma16816(acc[mt][2 * np + 1], al2[mt], &bh2[np][2]);
                }
        }
    }

#pragma unroll
    for (int mt = 0; mt < 2; mt++)
#pragma unroll
        for (int nt = 0; nt < 2 * NP; nt++) {
            int row = bm + wm + mt * 16 + g;
            int col = bn + wn + nt * 8 + cq * 2;
            *(float2*)&C[(size_t)row * N + col]       = make_float2(acc[mt][nt][0], acc[mt][nt][1]);
            *(float2*)&C[(size_t)(row + 8) * N + col] = make_float2(acc[mt][nt][2], acc[mt][nt][3]);
        }
}

// ---------------------------------------------------------------------------
// RoPE + split to fp16 planes. One 32-thread block per (s, q-or-k head).
// ---------------------------------------------------------------------------
__global__ void rope_split(const int* __restrict__ positions)
{
    const int row = blockIdx.x;
    const int s  = row / (NH_ + NKV_);
    const int hh = row % (NH_ + NKV_);
    const int i  = threadIdx.x;

    const float pos = (float)positions[s];
    const float inv_freq = powf(10000.0f, -(float)i / 32.0f);
    const float ang = pos * inv_freq;
    float c, sn;
    sincosf(ang, &sn, &c);

    const float* src;
    __half *dh, *dl;
    if (hh < NH_) {
        src = &g_qkv[(size_t)s * QKV_N_ + hh * HD_];
        dh = &g_qh[(size_t)s * (NH_ * HD_) + hh * HD_];
        dl = &g_ql[(size_t)s * (NH_ * HD_) + hh * HD_];
    } else {
        const int kvh = hh - NH_;
        src = &g_qkv[(size_t)s * QKV_N_ + KOFF_ + kvh * HD_];
        dh = &g_kh[(size_t)s * (NKV_ * HD_) + kvh * HD_];
        dl = &g_kl[(size_t)s * (NKV_ * HD_) + kvh * HD_];
    }
    const float x1 = src[i];
    const float x2 = src[i + 32];
    const float r1 = x1 * c - x2 * sn;
    const float r2 = x2 * c + x1 * sn;
    __half h1 = __float2half_rn(r1);
    __half h2 = __float2half_rn(r2);
    dh[i]      = h1;
    dh[i + 32] = h2;
    dl[i]      = __float2half_rn(r1 - __half2float(h1));
    dl[i + 32] = __float2half_rn(r2 - __half2float(h2));
}

// ---------------------------------------------------------------------------
// Flash attention fp16: 128-query tile, 256 threads (8 warps x 16 rows).
// Q 2-plane, K 2-plane (3-pass QK^T), P 2-plane, V single plane (2-pass PV).
// Q smem reused for K/V after fragment extraction. Per-warp causal tile skip.
// ---------------------------------------------------------------------------
#define VSTR 36

__global__ __launch_bounds__(256, 2)
void flash_attn(const float* __restrict__ sinks)
{
    __shared__ uint32_t SB[2 * 128 * VSTR];   // 36864 B; Q stage, then K(2)+V(1)

    const int h   = blockIdx.y;
    const int qt  = (S_ / 128 - 1) - blockIdx.x;   // heavy tiles first
    const int q0  = qt * 128;
    const int kv  = h >> 3;
    const int tid = threadIdx.x;
    const int wid = tid >> 5;                      // 0..7
    const int lane = tid & 31;
    const int g   = lane >> 2;
    const int cq  = lane & 3;
    const float sink = sinks[h];

    // ---- stage Q tile (both planes) ----
    {
        const int row = tid >> 1, e = tid & 1;
        const uint32_t* qh = (const uint32_t*)&g_qh[(size_t)(q0 + row) * (NH_ * HD_) + h * HD_ + e * 32];
        const uint32_t* ql = (const uint32_t*)&g_ql[(size_t)(q0 + row) * (NH_ * HD_) + h * HD_ + e * 32];
#pragma unroll
        for (int w = 0; w < 16; w++) {
            SB[row * VSTR + e * 16 + w]               = qh[w];
            SB[128 * VSTR + row * VSTR + e * 16 + w]  = ql[w];
        }
    }
    __syncthreads();

    // ---- Q fragments in registers ----
    uint32_t qa[2][4][4];
    {
        const int r0 = (wid * 16 + g) * VSTR;
        const int r8 = r0 + 8 * VSTR;
#pragma unroll
        for (int p = 0; p < 2; p++) {
            const int base = p * 128 * VSTR;
#pragma unroll
            for (int kt = 0; kt < 4; kt++) {
                const int w0 = kt * 8 + cq;
                qa[p][kt][0] = SB[base + r0 + w0];
                qa[p][kt][1] = SB[base + r8 + w0];
                qa[p][kt][2] = SB[base + r0 + w0 + 4];
                qa[p][kt][3] = SB[base + r8 + w0 + 4];
            }
        }
    }
    __syncthreads();   // Q smem free for K/V reuse

    uint32_t* Ks0 = SB;
    uint32_t* Ks1 = SB + 64 * VSTR;
    uint32_t* Vs  = SB + 128 * VSTR;

    float oacc[8][4];
#pragma unroll
    for (int nt = 0; nt < 8; nt++)
#pragma unroll
        for (int i = 0; i < 4; i++) oacc[nt][i] = 0.f;
    float m0 = -INFINITY, m8 = -INFINITY;
    float l0 = 0.f, l8 = 0.f;

    const int row_g  = q0 + wid * 16 + g;
    const int row_g8 = row_g + 8;
    const int wrow_max = q0 + wid * 16 + 15;
    const int ntiles = (q0 + 128) >> 6;

    for (int t = 0; t < ntiles; t++) {
        const int k0 = t * 64;
        __syncthreads();

        // stage K tile (2 planes): key = tid>>2, seg = tid&3 (8 words each)
        {
            const int key = tid >> 2, seg = tid & 3;
            const uint32_t* kh = (const uint32_t*)&g_kh[(size_t)(k0 + key) * (NKV_ * HD_) + kv * HD_];
            const uint32_t* kl = (const uint32_t*)&g_kl[(size_t)(k0 + key) * (NKV_ * HD_) + kv * HD_];
#pragma unroll
            for (int w = 0; w < 8; w++) {
                Ks0[key * VSTR + seg * 8 + w] = kh[seg * 8 + w];
                Ks1[key * VSTR + seg * 8 + w] = kl[seg * 8 + w];
            }
        }
        // stage V^T tile (single plane): d = tid>>2, seg = tid&3
        {
            const int d = tid >> 2, seg = tid & 3;
            const uint32_t* vh = (const uint32_t*)&g_vt[((size_t)kv * HD_ + d) * S_ + k0];
#pragma unroll
            for (int w = 0; w < 8; w++)
                Vs[d * VSTR + seg * 8 + w] = vh[seg * 8 + w];
        }
        __syncthreads();

        if (k0 > wrow_max) continue;   // fully-masked tile for this warp

        // ---- S = Q K^T (3-pass: qh*kh, qh*kl, ql*kh) ----
        float sacc[8][4];
#pragma unroll
        for (int nt = 0; nt < 8; nt++)
#pragma unroll
            for (int i = 0; i < 4; i++) sacc[nt][i] = 0.f;

#pragma unroll
        for (int kt = 0; kt < 4; kt++) {
            uint32_t kh[8][2], kl[8][2];
#pragma unroll
            for (int nt = 0; nt < 8; nt++) {
                const int r0 = (nt * 8 + g) * VSTR + kt * 8 + cq;
                kh[nt][0] = Ks0[r0]; kh[nt][1] = Ks0[r0 + 4];
                kl[nt][0] = Ks1[r0]; kl[nt][1] = Ks1[r0 + 4];
            }
#pragma unroll
            for (int nt = 0; nt < 8; nt++) mma16816(sacc[nt], qa[0][kt], kh[nt]);
#pragma unroll
            for (int nt = 0; nt < 8; nt++) mma16816(sacc[nt], qa[0][kt], kl[nt]);
#pragma unroll
            for (int nt = 0; nt < 8; nt++) mma16816(sacc[nt], qa[1][kt], kh[nt]);
        }

        // ---- scale + causal mask (diagonal tiles only) ----
        const bool need_mask = (k0 + 63 > row_g);
#pragma unroll
        for (int nt = 0; nt < 8; nt++) {
            const int c0 = k0 + nt * 8 + 2 * cq;
#pragma unroll
            for (int i = 0; i < 4; i++) sacc[nt][i] *= SCALE_;
            if (need_mask) {
                if (c0     > row_g)  sacc[nt][0] = -INFINITY;
                if (c0 + 1 > row_g)  sacc[nt][1] = -INFINITY;
                if (c0     > row_g8) sacc[nt][2] = -INFINITY;
                if (c0 + 1 > row_g8) sacc[nt][3] = -INFINITY;
            }
        }

        // ---- online softmax update ----
        float tm0 = -INFINITY, tm8 = -INFINITY;
#pragma unroll
        for (int nt = 0; nt < 8; nt++) {
            tm0 = fmaxf(tm0, fmaxf(sacc[nt][0], sacc[nt][1]));
            tm8 = fmaxf(tm8, fmaxf(sacc[nt][2], sacc[nt][3]));
        }
        tm0 = fmaxf(tm0, __shfl_xor_sync(0xffffffffu, tm0, 1));
        tm0 = fmaxf(tm0, __shfl_xor_sync(0xffffffffu, tm0, 2));
        tm8 = fmaxf(tm8, __shfl_xor_sync(0xffffffffu, tm8, 1));
        tm8 = fmaxf(tm8, __shfl_xor_sync(0xffffffffu, tm8, 2));

        const float m0n = fmaxf(m0, tm0);
        const float m8n = fmaxf(m8, tm8);
        const float a0 = __expf(m0 - m0n);
        const float a8 = __expf(m8 - m8n);
        m0 = m0n; m8 = m8n;
        l0 *= a0; l8 *= a8;
#pragma unroll
        for (int nt = 0; nt < 8; nt++) {
            oacc[nt][0] *= a0; oacc[nt][1] *= a0;
            oacc[nt][2] *= a8; oacc[nt][3] *= a8;
        }

#pragma unroll
        for (int nt = 0; nt < 8; nt++) {
            float p0 = (sacc[nt][0] == -INFINITY) ? 0.f : __expf(sacc[nt][0] - m0);
            float p1 = (sacc[nt][1] == -INFINITY) ? 0.f : __expf(sacc[nt][1] - m0);
            float p2 = (sacc[nt][2] == -INFINITY) ? 0.f : __expf(sacc[nt][2] - m8);
            float p3 = (sacc[nt][3] == -INFINITY) ? 0.f : __expf(sacc[nt][3] - m8);
            sacc[nt][0] = p0; sacc[nt][1] = p1; sacc[nt][2] = p2; sacc[nt][3] = p3;
            l0 += p0 + p1;
            l8 += p2 + p3;
        }

        // ---- O += P V (P 2-plane, V single: 2-pass) ----
#pragma unroll
        for (int kt = 0; kt < 4; kt++) {
            uint32_t pah[4], pal[4];
            split2h(sacc[2 * kt][0],     sacc[2 * kt][1],     pah[0], pal[0]);
            split2h(sacc[2 * kt][2],     sacc[2 * kt][3],     pah[1], pal[1]);
            split2h(sacc[2 * kt + 1][0], sacc[2 * kt + 1][1], pah[2], pal[2]);
            split2h(sacc[2 * kt + 1][2], sacc[2 * kt + 1][3], pah[3], pal[3]);
            uint32_t vh[8][2];
#pragma unroll
            for (int nt = 0; nt < 8; nt++) {
                const int r0 = (nt * 8 + g) * VSTR + kt * 8 + cq;
                vh[nt][0] = Vs[r0]; vh[nt][1] = Vs[r0 + 4];
            }
#pragma unroll
            for (int nt = 0; nt < 8; nt++) mma16816(oacc[nt], pah, vh[nt]);
#pragma unroll
            for (int nt = 0; nt < 8; nt++) mma16816(oacc[nt], pal, vh[nt]);
        }
    }

    // ---- finalize with sink; write fp16 hi/lo planes ----
    {
        const float m0n = fmaxf(m0, sink);
        const float m8n = fmaxf(m8, sink);
        const float a0 = __expf(m0 - m0n);
        const float a8 = __expf(m8 - m8n);
        l0 *= a0; l8 *= a8;
        l0 += __shfl_xor_sync(0xffffffffu, l0, 1);
        l0 += __shfl_xor_sync(0xffffffffu, l0, 2);
        l8 += __shfl_xor_sync(0xffffffffu, l8, 1);
        l8 += __shfl_xor_sync(0xffffffffu, l8, 2);
        const float inv0 = a0 / (l0 + __expf(sink - m0n));
        const float inv8 = a8 / (l8 + __expf(sink - m8n));
#pragma unroll
        for (int nt = 0; nt < 8; nt++) {
            const int col = h * HD_ + nt * 8 + 2 * cq;
            uint32_t hw, lw;
            split2h(oacc[nt][0] * inv0, oacc[nt][1] * inv0, hw, lw);
            *(uint32_t*)&g_ah[(size_t)row_g * ATTN_N_ + col] = hw;
            *(uint32_t*)&g_al[(size_t)row_g * ATTN_N_ + col] = lw;
            split2h(oacc[nt][2] * inv8, oacc[nt][3] * inv8, hw, lw);
            *(uint32_t*)&g_ah[(size_t)row_g8 * ATTN_N_ + col] = hw;
            *(uint32_t*)&g_al[(size_t)row_g8 * ATTN_N_ + col] = lw;
        }
    }
}

// ---------------------------------------------------------------------------
// Launch
// ---------------------------------------------------------------------------
extern "C" void kernel_launch(void* const* d_in, const int* in_sizes, int n_in,
                              void* d_out, int out_size)
{
    const int*   positions = (const int*)d_in[0];
    const float* hidden    = (const float*)d_in[1];
    const float* qkv_w     = (const float*)d_in[2];
    const float* o_w       = (const float*)d_in[3];
    const float* sinks     = (const float*)d_in[4];
    float*       out       = (float*)d_out;

    const int smem128 = 2 * (2 * BM + 128) * ASTR * (int)sizeof(__half);  // 61440
    const int smem96  = 2 * (2 * BM + 96)  * ASTR * (int)sizeof(__half);  // 56320

    static bool attr_done = false;
    if (!attr_done) {
        cudaFuncSetAttribute(gemm_2p<128>, cudaFuncAttributeMaxDynamicSharedMemorySize, smem128);
        cudaFuncSetAttribute(gemm_2p<96>,  cudaFuncAttributeMaxDynamicSharedMemorySize, smem96);
        attr_done = true;
    }

    void *p;
    cudaGetSymbolAddress(&p, g_qkv);  float* qkv = (float*)p;
    cudaGetSymbolAddress(&p, g_wq);   __half* wq = (__half*)p;
    cudaGetSymbolAddress(&p, g_wo);   __half* wo = (__half*)p;
    cudaGetSymbolAddress(&p, g_xh);   __half* xh = (__half*)p;
    cudaGetSymbolAddress(&p, g_xl);   __half* xl = (__half*)p;
    cudaGetSymbolAddress(&p, g_ah);   __half* ah = (__half*)p;
    cudaGetSymbolAddress(&p, g_al);   __half* al = (__half*)p;

    // 0) pre-convert: weights single fp16 plane, hidden 2-plane fp16
    cvt_f16<<<(QKV_N_ * H_) / 1024, 256>>>(qkv_w, wq, QKV_N_ * H_);
    cvt_f16<<<(H_ * ATTN_N_) / 1024, 256>>>(o_w, wo, H_ * ATTN_N_);
    split_f16<<<(S_ * H_) / 1024, 256>>>(hidden, xh, xl, S_ * H_);

    // 1) QKV projection: [1024,2880] @ [5120,2880]^T -> g_qkv fp32
    gemm_2p<128><<<dim3(QKV_N_ / 128, S_ / BM), 256, smem128>>>(xh, xl, wq, qkv, S_, QKV_N_, H_);

    // 2) RoPE + split Q/K; transpose + convert V
    rope_split<<<S_ * (NH_ + NKV_), 32>>>(positions);
    vcvt_t<<<dim3(S_ / 32, NKV_), 256>>>();

    // 3) Flash attention -> attn planes (128-query tiles)
    flash_attn<<<dim3(S_ / 128, NH_), 256>>>(sinks);

    // 4) O projection: attn planes @ o_w plane -> out fp32
    gemm_2p<96><<<dim3(H_ / 96, S_ / BM), 256, smem96>>>(ah, al, wo, out, S_, H_, ATTN_N_);
}

// round 15
// speedup vs baseline: 1.5495x; 1.0998x over previous
#include <cuda_runtime.h>
#include <cuda_bf16.h>
#include <cuda_fp16.h>
#include <math.h>
#include <stdint.h>

// Problem constants
#define S_   1024
#define H_   2880
#define NH_  64
#define NKV_ 8
#define HD_  64
#define QKV_N_ 5120              // (NH + 2*NKV) * HD
#define KOFF_  4096              // NH*HD
#define VOFF_  4608              // NH*HD + NKV*HD
#define ATTN_N_ 4096             // NH*HD
#define SCALE_ 0.125f            // HD^-0.5

// ---------------------------------------------------------------------------
// Scratch (allocation-free: __device__ globals). fp16 planes.
// ---------------------------------------------------------------------------
__device__ float g_qkv[S_ * QKV_N_];             // 20 MB (pre-rope)
__device__ __half g_wq[QKV_N_ * H_];             // qkv_w single fp16 plane
__device__ __half g_wo[H_ * ATTN_N_];            // o_w single fp16 plane
__device__ __half g_xh[S_ * H_];                 // hidden hi
__device__ __half g_xl[S_ * H_];                 // hidden lo
__device__ __half g_qh[S_ * NH_ * HD_];          // roped Q hi
__device__ __half g_ql[S_ * NH_ * HD_];
__device__ __half g_kh[S_ * NKV_ * HD_];         // roped K hi
__device__ __half g_kl[S_ * NKV_ * HD_];
__device__ __half g_vt[NKV_ * HD_ * S_];         // V^T single plane: [kv][d][s]
__device__ __half g_ah[S_ * ATTN_N_];            // attn out hi
__device__ __half g_al[S_ * ATTN_N_];

// ---------------------------------------------------------------------------
// Helpers
// ---------------------------------------------------------------------------
__device__ __forceinline__ void mma16816(float* c, const uint32_t* a, const uint32_t* b) {
    asm volatile(
        "mma.sync.aligned.m16n8k16.row.col.f32.f16.f16.f32 "
        "{%0,%1,%2,%3}, {%4,%5,%6,%7}, {%8,%9}, {%0,%1,%2,%3};\n"
        : "+f"(c[0]), "+f"(c[1]), "+f"(c[2]), "+f"(c[3])
        : "r"(a[0]), "r"(a[1]), "r"(a[2]), "r"(a[3]), "r"(b[0]), "r"(b[1]));
}

__device__ __forceinline__ void split2h(float x, float y, uint32_t& hi, uint32_t& lo) {
    __half hx = __float2half_rn(x);
    __half hy = __float2half_rn(y);
    __half lx = __float2half_rn(x - __half2float(hx));
    __half ly = __float2half_rn(y - __half2float(hy));
    hi = ((uint32_t)__half_as_ushort(hy) << 16) | (uint32_t)__half_as_ushort(hx);
    lo = ((uint32_t)__half_as_ushort(ly) << 16) | (uint32_t)__half_as_ushort(lx);
}

__device__ __forceinline__ uint32_t smemu32(const void* p) {
    return (uint32_t)__cvta_generic_to_shared(p);
}

#define LDSM4(R0, R1, R2, R3, addr) \
    asm volatile("ldmatrix.sync.aligned.m8n8.x4.shared.b16 {%0,%1,%2,%3}, [%4];" \
                 : "=r"(R0), "=r"(R1), "=r"(R2), "=r"(R3) : "r"(addr))

#define CP16(dst, src) \
    asm volatile("cp.async.cg.shared.global [%0], [%1], 16;" :: "r"(dst), "l"(src))

// ---------------------------------------------------------------------------
// fp32 -> fp16 hi/lo plane split (vectorized)
// ---------------------------------------------------------------------------
__global__ __launch_bounds__(256)
void split_f16(const float* __restrict__ in, __half* __restrict__ hi,
               __half* __restrict__ lo, int n)
{
    int i = (blockIdx.x * 256 + threadIdx.x) * 4;
    if (i >= n) return;
    float4 v = *(const float4*)&in[i];
    uint32_t h0, l0, h1, l1;
    split2h(v.x, v.y, h0, l0);
    split2h(v.z, v.w, h1, l1);
    uint32_t* ph = (uint32_t*)&hi[i];
    uint32_t* pl = (uint32_t*)&lo[i];
    ph[0] = h0; ph[1] = h1;
    pl[0] = l0; pl[1] = l1;
}

// fp32 -> single fp16 plane
__global__ __launch_bounds__(256)
void cvt_f16(const float* __restrict__ in, __half* __restrict__ out, int n)
{
    int i = (blockIdx.x * 256 + threadIdx.x) * 4;
    if (i >= n) return;
    float4 v = *(const float4*)&in[i];
    __half2* o = (__half2*)&out[i];
    o[0] = __floats2half2_rn(v.x, v.y);
    o[1] = __floats2half2_rn(v.z, v.w);
}

// ---------------------------------------------------------------------------
// V transpose + convert: g_qkv V section fp32 [s][kv][d] -> g_vt[kv][d][s] fp16
// ---------------------------------------------------------------------------
__global__ __launch_bounds__(256)
void vcvt_t()
{
    __shared__ float tile[32][65];
    const int s0 = blockIdx.x * 32;
    const int kv = blockIdx.y;
    const int tid = threadIdx.x;

    {
        const int sl = tid >> 3;
        const int dc = (tid & 7) * 8;
        const float* src = &g_qkv[(size_t)(s0 + sl) * QKV_N_ + VOFF_ + kv * HD_ + dc];
        float4 a = *(const float4*)&src[0];
        float4 b = *(const float4*)&src[4];
        tile[sl][dc + 0] = a.x; tile[sl][dc + 1] = a.y;
        tile[sl][dc + 2] = a.z; tile[sl][dc + 3] = a.w;
        tile[sl][dc + 4] = b.x; tile[sl][dc + 5] = b.y;
        tile[sl][dc + 6] = b.z; tile[sl][dc + 7] = b.w;
    }
    __syncthreads();

    {
        const int d  = tid >> 2;
        const int p0 = (tid & 3) * 4;
        __half2* dst = (__half2*)&g_vt[((size_t)kv * HD_ + d) * S_ + s0];
#pragma unroll
        for (int i = 0; i < 4; i++) {
            const int p = p0 + i;
            dst[p] = __floats2half2_rn(tile[2 * p][d], tile[2 * p + 1][d]);
        }
    }
}

// ---------------------------------------------------------------------------
// Tensor-core GEMM (NT): C[m,n] = sum_k A[m,k]*B[n,k]
// A = Ah + Al (2-plane fp16), B = single fp16 plane. 2-pass, fp32 acc.
// BM=128, BN=64, BK=64 (fewer syncs), 256 threads, warp tile 32x32.
// ---------------------------------------------------------------------------
#define BM 128
#define BN 64
#define BK 64
#define ASTR 72                              // 64 data + 8 pad halves; 144B rows
#define GR   (2 * BM + BN)                   // 320 rows per buffer
#define BUFE (GR * ASTR)                     // halves per buffer

__global__ __launch_bounds__(256, 2)
void gemm_2p(const __half* __restrict__ Ah, const __half* __restrict__ Al,
             const __half* __restrict__ Bp,
             float* __restrict__ C, int M, int N, int K)
{
    extern __shared__ __half sm[];

    const int tid  = threadIdx.x;
    const int wid  = tid >> 5;
    const int lane = tid & 31;
    const int g    = lane >> 2;
    const int cq   = lane & 3;
    const int wm   = (wid & 3) * 32;
    const int wn   = (wid >> 2) * 32;
    const int bm   = blockIdx.y * BM;
    const int bn   = blockIdx.x * BN;

    float acc[2][4][4];
#pragma unroll
    for (int mt = 0; mt < 2; mt++)
#pragma unroll
        for (int nt = 0; nt < 4; nt++)
#pragma unroll
            for (int i = 0; i < 4; i++) acc[mt][nt][i] = 0.f;

    const int ntile = K / BK;

    // 10 x 16B chunks per thread per stage (320 rows x 8 chunks / 256 thr)
    auto load_tile = [&](int t, int buf) {
        const int k0 = t * BK;
        __half* s = sm + buf * BUFE;
#pragma unroll
        for (int i = 0; i < 10; i++) {
            int c = tid + i * 256;
            int r = c >> 3, col = (c & 7) * 8;
            const __half* src;
            if (r < BM)            src = Ah + (size_t)(bm + r) * K + k0 + col;
            else if (r < 2 * BM)   src = Al + (size_t)(bm + r - BM) * K + k0 + col;
            else                   src = Bp + (size_t)(bn + r - 2 * BM) * K + k0 + col;
            CP16(smemu32(s + r * ASTR + col), src);
        }
        asm volatile("cp.async.commit_group;" ::);
    };

    load_tile(0, 0);

    const int lr  = lane & 15;
    const int hb  = (lane >> 4) * 8;
    const int l8  = lane & 7;
    const int sel = lane >> 3;

    for (int t = 0; t < ntile; t++) {
        asm volatile("cp.async.wait_group 0;" ::);
        __syncthreads();
        if (t + 1 < ntile) load_tile(t + 1, (t + 1) & 1);

        const __half* s = sm + (t & 1) * BUFE;
#pragma unroll
        for (int kk = 0; kk < 4; kk++) {
            uint32_t ah2[2][4], al2[2][4], bh2[2][4];
#pragma unroll
            for (int mt = 0; mt < 2; mt++) {
                uint32_t addr = smemu32(s + (wm + mt * 16 + lr) * ASTR + kk * 16 + hb);
                LDSM4(ah2[mt][0], ah2[mt][1], ah2[mt][2], ah2[mt][3], addr);
                addr = smemu32(s + BM * ASTR + (wm + mt * 16 + lr) * ASTR + kk * 16 + hb);
                LDSM4(al2[mt][0], al2[mt][1], al2[mt][2], al2[mt][3], addr);
            }
#pragma unroll
            for (int np = 0; np < 2; np++) {
                const int brow = wn + np * 16 + ((sel >> 1) << 3) + l8;
                const int bcol = kk * 16 + (sel & 1) * 8;
                LDSM4(bh2[np][0], bh2[np][1], bh2[np][2], bh2[np][3],
                      smemu32(s + 2 * BM * ASTR + brow * ASTR + bcol));
            }
            // pass 1: Ah * B
#pragma unroll
            for (int mt = 0; mt < 2; mt++)
#pragma unroll
                for (int np = 0; np < 2; np++) {
                    mma16816(acc[mt][2 * np],     ah2[mt], &bh2[np][0]);
                    mma16816(acc[mt][2 * np + 1], ah2[mt], &bh2[np][2]);
                }
            // pass 2: Al * B
#pragma unroll
            for (int mt = 0; mt < 2; mt++)
#pragma unroll
                for (int np = 0; np < 2; np++) {
                    mma16816(acc[mt][2 * np],     al2[mt], &bh2[np][0]);
                    mma16816(acc[mt][2 * np + 1], al2[mt], &bh2[np][2]);
                }
        }
    }

#pragma unroll
    for (int mt = 0; mt < 2; mt++)
#pragma unroll
        for (int nt = 0; nt < 4; nt++) {
            int row = bm + wm + mt * 16 + g;
            int col = bn + wn + nt * 8 + cq * 2;
            *(float2*)&C[(size_t)row * N + col]       = make_float2(acc[mt][nt][0], acc[mt][nt][1]);
            *(float2*)&C[(size_t)(row + 8) * N + col] = make_float2(acc[mt][nt][2], acc[mt][nt][3]);
        }
}

// ---------------------------------------------------------------------------
// RoPE + split to fp16 planes. One 32-thread block per (s, q-or-k head).
// ---------------------------------------------------------------------------
__global__ void rope_split(const int* __restrict__ positions)
{
    const int row = blockIdx.x;
    const int s  = row / (NH_ + NKV_);
    const int hh = row % (NH_ + NKV_);
    const int i  = threadIdx.x;

    const float pos = (float)positions[s];
    const float inv_freq = powf(10000.0f, -(float)i / 32.0f);
    const float ang = pos * inv_freq;
    float c, sn;
    sincosf(ang, &sn, &c);

    const float* src;
    __half *dh, *dl;
    if (hh < NH_) {
        src = &g_qkv[(size_t)s * QKV_N_ + hh * HD_];
        dh = &g_qh[(size_t)s * (NH_ * HD_) + hh * HD_];
        dl = &g_ql[(size_t)s * (NH_ * HD_) + hh * HD_];
    } else {
        const int kvh = hh - NH_;
        src = &g_qkv[(size_t)s * QKV_N_ + KOFF_ + kvh * HD_];
        dh = &g_kh[(size_t)s * (NKV_ * HD_) + kvh * HD_];
        dl = &g_kl[(size_t)s * (NKV_ * HD_) + kvh * HD_];
    }
    const float x1 = src[i];
    const float x2 = src[i + 32];
    const float r1 = x1 * c - x2 * sn;
    const float r2 = x2 * c + x1 * sn;
    __half h1 = __float2half_rn(r1);
    __half h2 = __float2half_rn(r2);
    dh[i]      = h1;
    dh[i + 32] = h2;
    dl[i]      = __float2half_rn(r1 - __half2float(h1));
    dl[i + 32] = __float2half_rn(r2 - __half2float(h2));
}

// ---------------------------------------------------------------------------
// Flash attention fp16: 128-query tile, 256 threads (8 warps x 16 rows).
// Q 2-plane, K 2-plane (3-pass QK^T), P 2-plane, V single plane (2-pass PV).
// Q smem reused for K/V after fragment extraction. Per-warp causal tile skip.
// ---------------------------------------------------------------------------
#define VSTR 36

__global__ __launch_bounds__(256, 2)
void flash_attn(const float* __restrict__ sinks)
{
    __shared__ uint32_t SB[2 * 128 * VSTR];   // 36864 B; Q stage, then K(2)+V(1)

    const int h   = blockIdx.y;
    const int qt  = (S_ / 128 - 1) - blockIdx.x;   // heavy tiles first
    const int q0  = qt * 128;
    const int kv  = h >> 3;
    const int tid = threadIdx.x;
    const int wid = tid >> 5;                      // 0..7
    const int lane = tid & 31;
    const int g   = lane >> 2;
    const int cq  = lane & 3;
    const float sink = sinks[h];

    // ---- stage Q tile (both planes) ----
    {
        const int row = tid >> 1, e = tid & 1;
        const uint32_t* qh = (const uint32_t*)&g_qh[(size_t)(q0 + row) * (NH_ * HD_) + h * HD_ + e * 32];
        const uint32_t* ql = (const uint32_t*)&g_ql[(size_t)(q0 + row) * (NH_ * HD_) + h * HD_ + e * 32];
#pragma unroll
        for (int w = 0; w < 16; w++) {
            SB[row * VSTR + e * 16 + w]               = qh[w];
            SB[128 * VSTR + row * VSTR + e * 16 + w]  = ql[w];
        }
    }
    __syncthreads();

    // ---- Q fragments in registers ----
    uint32_t qa[2][4][4];
    {
        const int r0 = (wid * 16 + g) * VSTR;
        const int r8 = r0 + 8 * VSTR;
#pragma unroll
        for (int p = 0; p < 2; p++) {
            const int base = p * 128 * VSTR;
#pragma unroll
            for (int kt = 0; kt < 4; kt++) {
                const int w0 = kt * 8 + cq;
                qa[p][kt][0] = SB[base + r0 + w0];
                qa[p][kt][1] = SB[base + r8 + w0];
                qa[p][kt][2] = SB[base + r0 + w0 + 4];
                qa[p][kt][3] = SB[base + r8 + w0 + 4];
            }
        }
    }
    __syncthreads();   // Q smem free for K/V reuse

    uint32_t* Ks0 = SB;
    uint32_t* Ks1 = SB + 64 * VSTR;
    uint32_t* Vs  = SB + 128 * VSTR;

    float oacc[8][4];
#pragma unroll
    for (int nt = 0; nt < 8; nt++)
#pragma unroll
        for (int i = 0; i < 4; i++) oacc[nt][i] = 0.f;
    float m0 = -INFINITY, m8 = -INFINITY;
    float l0 = 0.f, l8 = 0.f;

    const int row_g  = q0 + wid * 16 + g;
    const int row_g8 = row_g + 8;
    const int wrow_max = q0 + wid * 16 + 15;
    const int ntiles = (q0 + 128) >> 6;

    for (int t = 0; t < ntiles; t++) {
        const int k0 = t * 64;
        __syncthreads();

        // stage K tile (2 planes): key = tid>>2, seg = tid&3 (8 words each)
        {
            const int key = tid >> 2, seg = tid & 3;
            const uint32_t* kh = (const uint32_t*)&g_kh[(size_t)(k0 + key) * (NKV_ * HD_) + kv * HD_];
            const uint32_t* kl = (const uint32_t*)&g_kl[(size_t)(k0 + key) * (NKV_ * HD_) + kv * HD_];
#pragma unroll
            for (int w = 0; w < 8; w++) {
                Ks0[key * VSTR + seg * 8 + w] = kh[seg * 8 + w];
                Ks1[key * VSTR + seg * 8 + w] = kl[seg * 8 + w];
            }
        }
        // stage V^T tile (single plane): d = tid>>2, seg = tid&3
        {
            const int d = tid >> 2, seg = tid & 3;
            const uint32_t* vh = (const uint32_t*)&g_vt[((size_t)kv * HD_ + d) * S_ + k0];
#pragma unroll
            for (int w = 0; w < 8; w++)
                Vs[d * VSTR + seg * 8 + w] = vh[seg * 8 + w];
        }
        __syncthreads();

        if (k0 > wrow_max) continue;   // fully-masked tile for this warp

        // ---- S = Q K^T (3-pass: qh*kh, qh*kl, ql*kh) ----
        float sacc[8][4];
#pragma unroll
        for (int nt = 0; nt < 8; nt++)
#pragma unroll
            for (int i = 0; i < 4; i++) sacc[nt][i] = 0.f;

#pragma unroll
        for (int kt = 0; kt < 4; kt++) {
            uint32_t kh[8][2], kl[8][2];
#pragma unroll
            for (int nt = 0; nt < 8; nt++) {
                const int r0 = (nt * 8 + g) * VSTR + kt * 8 + cq;
                kh[nt][0] = Ks0[r0]; kh[nt][1] = Ks0[r0 + 4];
                kl[nt][0] = Ks1[r0]; kl[nt][1] = Ks1[r0 + 4];
            }
#pragma unroll
            for (int nt = 0; nt < 8; nt++) mma16816(sacc[nt], qa[0][kt], kh[nt]);
#pragma unroll
            for (int nt = 0; nt < 8; nt++) mma16816(sacc[nt], qa[0][kt], kl[nt]);
#pragma unroll
            for (int nt = 0; nt < 8; nt++) mma16816(sacc[nt], qa[1][kt], kh[nt]);
        }

        // ---- scale + causal mask (diagonal tiles only) ----
        const bool need_mask = (k0 + 63 > row_g);
#pragma unroll
        for (int nt = 0; nt < 8; nt++) {
            const int c0 = k0 + nt * 8 + 2 * cq;
#pragma unroll
            for (int i = 0; i < 4; i++) sacc[nt][i] *= SCALE_;
            if (need_mask) {
                if (c0     > row_g)  sacc[nt][0] = -INFINITY;
                if (c0 + 1 > row_g)  sacc[nt][1] = -INFINITY;
                if (c0     > row_g8) sacc[nt][2] = -INFINITY;
                if (c0 + 1 > row_g8) sacc[nt][3] = -INFINITY;
            }
        }

        // ---- online softmax update ----
        float tm0 = -INFINITY, tm8 = -INFINITY;
#pragma unroll
        for (int nt = 0; nt < 8; nt++) {
            tm0 = fmaxf(tm0, fmaxf(sacc[nt][0], sacc[nt][1]));
            tm8 = fmaxf(tm8, fmaxf(sacc[nt][2], sacc[nt][3]));
        }
        tm0 = fmaxf(tm0, __shfl_xor_sync(0xffffffffu, tm0, 1));
        tm0 = fmaxf(tm0, __shfl_xor_sync(0xffffffffu, tm0, 2));
        tm8 = fmaxf(tm8, __shfl_xor_sync(0xffffffffu, tm8, 1));
        tm8 = fmaxf(tm8, __shfl_xor_sync(0xffffffffu, tm8, 2));

        const float m0n = fmaxf(m0, tm0);
        const float m8n = fmaxf(m8, tm8);
        const float a0 = __expf(m0 - m0n);
        const float a8 = __expf(m8 - m8n);
        m0 = m0n; m8 = m8n;
        l0 *= a0; l8 *= a8;
#pragma unroll
        for (int nt = 0; nt < 8; nt++) {
            oacc[nt][0] *= a0; oacc[nt][1] *= a0;
            oacc[nt][2] *= a8; oacc[nt][3] *= a8;
        }

#pragma unroll
        for (int nt = 0; nt < 8; nt++) {
            float p0 = (sacc[nt][0] == -INFINITY) ? 0.f : __expf(sacc[nt][0] - m0);
            float p1 = (sacc[nt][1] == -INFINITY) ? 0.f : __expf(sacc[nt][1] - m0);
            float p2 = (sacc[nt][2] == -INFINITY) ? 0.f : __expf(sacc[nt][2] - m8);
            float p3 = (sacc[nt][3] == -INFINITY) ? 0.f : __expf(sacc[nt][3] - m8);
            sacc[nt][0] = p0; sacc[nt][1] = p1; sacc[nt][2] = p2; sacc[nt][3] = p3;
            l0 += p0 + p1;
            l8 += p2 + p3;
        }

        // ---- O += P V (P 2-plane, V single: 2-pass) ----
#pragma unroll
        for (int kt = 0; kt < 4; kt++) {
            uint32_t pah[4], pal[4];
            split2h(sacc[2 * kt][0],     sacc[2 * kt][1],     pah[0], pal[0]);
            split2h(sacc[2 * kt][2],     sacc[2 * kt][3],     pah[1], pal[1]);
            split2h(sacc[2 * kt + 1][0], sacc[2 * kt + 1][1], pah[2], pal[2]);
            split2h(sacc[2 * kt + 1][2], sacc[2 * kt + 1][3], pah[3], pal[3]);
            uint32_t vh[8][2];
#pragma unroll
            for (int nt = 0; nt < 8; nt++) {
                const int r0 = (nt * 8 + g) * VSTR + kt * 8 + cq;
                vh[nt][0] = Vs[r0]; vh[nt][1] = Vs[r0 + 4];
            }
#pragma unroll
            for (int nt = 0; nt < 8; nt++) mma16816(oacc[nt], pah, vh[nt]);
#pragma unroll
            for (int nt = 0; nt < 8; nt++) mma16816(oacc[nt], pal, vh[nt]);
        }
    }

    // ---- finalize with sink; write fp16 hi/lo planes ----
    {
        const float m0n = fmaxf(m0, sink);
        const float m8n = fmaxf(m8, sink);
        const float a0 = __expf(m0 - m0n);
        const float a8 = __expf(m8 - m8n);
        l0 *= a0; l8 *= a8;
        l0 += __shfl_xor_sync(0xffffffffu, l0, 1);
        l0 += __shfl_xor_sync(0xffffffffu, l0, 2);
        l8 += __shfl_xor_sync(0xffffffffu, l8, 1);
        l8 += __shfl_xor_sync(0xffffffffu, l8, 2);
        const float inv0 = a0 / (l0 + __expf(sink - m0n));
        const float inv8 = a8 / (l8 + __expf(sink - m8n));
#pragma unroll
        for (int nt = 0; nt < 8; nt++) {
            const int col = h * HD_ + nt * 8 + 2 * cq;
            uint32_t hw, lw;
            split2h(oacc[nt][0] * inv0, oacc[nt][1] * inv0, hw, lw);
            *(uint32_t*)&g_ah[(size_t)row_g * ATTN_N_ + col] = hw;
            *(uint32_t*)&g_al[(size_t)row_g * ATTN_N_ + col] = lw;
            split2h(oacc[nt][2] * inv8, oacc[nt][3] * inv8, hw, lw);
            *(uint32_t*)&g_ah[(size_t)row_g8 * ATTN_N_ + col] = hw;
            *(uint32_t*)&g_al[(size_t)row_g8 * ATTN_N_ + col] = lw;
        }
    }
}

// ---------------------------------------------------------------------------
// Launch
// ---------------------------------------------------------------------------
extern "C" void kernel_launch(void* const* d_in, const int* in_sizes, int n_in,
                              void* d_out, int out_size)
{
    const int*   positions = (const int*)d_in[0];
    const float* hidden    = (const float*)d_in[1];
    const float* qkv_w     = (const float*)d_in[2];
    const float* o_w       = (const float*)d_in[3];
    const float* sinks     = (const float*)d_in[4];
    float*       out       = (float*)d_out;

    const int smem = 2 * BUFE * (int)sizeof(__half);   // 92160 B

    static bool attr_done = false;
    if (!attr_done) {
        cudaFuncSetAttribute(gemm_2p, cudaFuncAttributeMaxDynamicSharedMemorySize, smem);
        attr_done = true;
    }

    void *p;
    cudaGetSymbolAddress(&p, g_qkv);  float* qkv = (float*)p;
    cudaGetSymbolAddress(&p, g_wq);   __half* wq = (__half*)p;
    cudaGetSymbolAddress(&p, g_wo);   __half* wo = (__half*)p;
    cudaGetSymbolAddress(&p, g_xh);   __half* xh = (__half*)p;
    cudaGetSymbolAddress(&p, g_xl);   __half* xl = (__half*)p;
    cudaGetSymbolAddress(&p, g_ah);   __half* ah = (__half*)p;
    cudaGetSymbolAddress(&p, g_al);   __half* al = (__half*)p;

    // 0) pre-convert: weights single fp16 plane, hidden 2-plane fp16
    cvt_f16<<<(QKV_N_ * H_) / 1024, 256>>>(qkv_w, wq, QKV_N_ * H_);
    cvt_f16<<<(H_ * ATTN_N_) / 1024, 256>>>(o_w, wo, H_ * ATTN_N_);
    split_f16<<<(S_ * H_) / 1024, 256>>>(hidden, xh, xl, S_ * H_);

    // 1) QKV projection: [1024,2880] @ [5120,2880]^T -> g_qkv fp32
    gemm_2p<<<dim3(QKV_N_ / BN, S_ / BM), 256, smem>>>(xh, xl, wq, qkv, S_, QKV_N_, H_);

    // 2) RoPE + split Q/K; transpose + convert V
    rope_split<<<S_ * (NH_ + NKV_), 32>>>(positions);
    vcvt_t<<<dim3(S_ / 32, NKV_), 256>>>();

    // 3) Flash attention -> attn planes (128-query tiles)
    flash_attn<<<dim3(S_ / 128, NH_), 256>>>(sinks);

    // 4) O projection: attn planes @ o_w plane -> out fp32
    gemm_2p<<<dim3(H_ / BN, S_ / BM), 256, smem>>>(ah, al, wo, out, S_, H_, ATTN_N_);
}

// round 16
// speedup vs baseline: 1.7659x; 1.1397x over previous
#include <cuda_runtime.h>
#include <cuda_bf16.h>
#include <cuda_fp16.h>
#include <math.h>
#include <stdint.h>

// Problem constants
#define S_   1024
#define H_   2880
#define NH_  64
#define NKV_ 8
#define HD_  64
#define QKV_N_ 5120              // (NH + 2*NKV) * HD
#define KOFF_  4096              // NH*HD
#define VOFF_  4608              // NH*HD + NKV*HD
#define ATTN_N_ 4096             // NH*HD
#define SCALE_ 0.125f            // HD^-0.5

// ---------------------------------------------------------------------------
// Scratch (allocation-free: __device__ globals). fp16 planes.
// ---------------------------------------------------------------------------
__device__ float g_qkv[S_ * QKV_N_];             // 20 MB (pre-rope)
__device__ __half g_wq[QKV_N_ * H_];             // qkv_w single fp16 plane
__device__ __half g_wo[H_ * ATTN_N_];            // o_w single fp16 plane
__device__ __half g_xh[S_ * H_];                 // hidden hi
__device__ __half g_xl[S_ * H_];                 // hidden lo
__device__ __half g_qh[S_ * NH_ * HD_];          // roped Q hi
__device__ __half g_ql[S_ * NH_ * HD_];
__device__ __half g_kh[S_ * NKV_ * HD_];         // roped K hi
__device__ __half g_kl[S_ * NKV_ * HD_];
__device__ __half g_vt[NKV_ * HD_ * S_];         // V^T single plane: [kv][d][s]
__device__ __half g_ah[S_ * ATTN_N_];            // attn out hi
__device__ __half g_al[S_ * ATTN_N_];

// ---------------------------------------------------------------------------
// Helpers
// ---------------------------------------------------------------------------
__device__ __forceinline__ void mma16816(float* c, const uint32_t* a, const uint32_t* b) {
    asm volatile(
        "mma.sync.aligned.m16n8k16.row.col.f32.f16.f16.f32 "
        "{%0,%1,%2,%3}, {%4,%5,%6,%7}, {%8,%9}, {%0,%1,%2,%3};\n"
        : "+f"(c[0]), "+f"(c[1]), "+f"(c[2]), "+f"(c[3])
        : "r"(a[0]), "r"(a[1]), "r"(a[2]), "r"(a[3]), "r"(b[0]), "r"(b[1]));
}

__device__ __forceinline__ void split2h(float x, float y, uint32_t& hi, uint32_t& lo) {
    __half hx = __float2half_rn(x);
    __half hy = __float2half_rn(y);
    __half lx = __float2half_rn(x - __half2float(hx));
    __half ly = __float2half_rn(y - __half2float(hy));
    hi = ((uint32_t)__half_as_ushort(hy) << 16) | (uint32_t)__half_as_ushort(hx);
    lo = ((uint32_t)__half_as_ushort(ly) << 16) | (uint32_t)__half_as_ushort(lx);
}

__device__ __forceinline__ uint32_t smemu32(const void* p) {
    return (uint32_t)__cvta_generic_to_shared(p);
}

#define LDSM4(R0, R1, R2, R3, addr) \
    asm volatile("ldmatrix.sync.aligned.m8n8.x4.shared.b16 {%0,%1,%2,%3}, [%4];" \
                 : "=r"(R0), "=r"(R1), "=r"(R2), "=r"(R3) : "r"(addr))

#define CP16(dst, src) \
    asm volatile("cp.async.cg.shared.global [%0], [%1], 16;" :: "r"(dst), "l"(src))

// ---------------------------------------------------------------------------
// fp32 -> fp16 hi/lo plane split (vectorized)
// ---------------------------------------------------------------------------
__global__ __launch_bounds__(256)
void split_f16(const float* __restrict__ in, __half* __restrict__ hi,
               __half* __restrict__ lo, int n)
{
    int i = (blockIdx.x * 256 + threadIdx.x) * 4;
    if (i >= n) return;
    float4 v = *(const float4*)&in[i];
    uint32_t h0, l0, h1, l1;
    split2h(v.x, v.y, h0, l0);
    split2h(v.z, v.w, h1, l1);
    uint32_t* ph = (uint32_t*)&hi[i];
    uint32_t* pl = (uint32_t*)&lo[i];
    ph[0] = h0; ph[1] = h1;
    pl[0] = l0; pl[1] = l1;
}

// fp32 -> single fp16 plane
__global__ __launch_bounds__(256)
void cvt_f16(const float* __restrict__ in, __half* __restrict__ out, int n)
{
    int i = (blockIdx.x * 256 + threadIdx.x) * 4;
    if (i >= n) return;
    float4 v = *(const float4*)&in[i];
    __half2* o = (__half2*)&out[i];
    o[0] = __floats2half2_rn(v.x, v.y);
    o[1] = __floats2half2_rn(v.z, v.w);
}

// ---------------------------------------------------------------------------
// V transpose + convert: g_qkv V section fp32 [s][kv][d] -> g_vt[kv][d][s] fp16
// ---------------------------------------------------------------------------
__global__ __launch_bounds__(256)
void vcvt_t()
{
    __shared__ float tile[32][65];
    const int s0 = blockIdx.x * 32;
    const int kv = blockIdx.y;
    const int tid = threadIdx.x;

    {
        const int sl = tid >> 3;
        const int dc = (tid & 7) * 8;
        const float* src = &g_qkv[(size_t)(s0 + sl) * QKV_N_ + VOFF_ + kv * HD_ + dc];
        float4 a = *(const float4*)&src[0];
        float4 b = *(const float4*)&src[4];
        tile[sl][dc + 0] = a.x; tile[sl][dc + 1] = a.y;
        tile[sl][dc + 2] = a.z; tile[sl][dc + 3] = a.w;
        tile[sl][dc + 4] = b.x; tile[sl][dc + 5] = b.y;
        tile[sl][dc + 6] = b.z; tile[sl][dc + 7] = b.w;
    }
    __syncthreads();

    {
        const int d  = tid >> 2;
        const int p0 = (tid & 3) * 4;
        __half2* dst = (__half2*)&g_vt[((size_t)kv * HD_ + d) * S_ + s0];
#pragma unroll
        for (int i = 0; i < 4; i++) {
            const int p = p0 + i;
            dst[p] = __floats2half2_rn(tile[2 * p][d], tile[2 * p + 1][d]);
        }
    }
}

// ---------------------------------------------------------------------------
// Tensor-core GEMM (NT): C[m,n] = sum_k A[m,k]*B[n,k]
// A = Ah + Al (2-plane fp16), B = single fp16 plane. 2-pass, fp32 acc.
// BM=128, BN=64, BK=64, 256 threads, warp tile 32x32.  (R15 winner, unchanged)
// ---------------------------------------------------------------------------
#define BM 128
#define BN 64
#define BK 64
#define ASTR 72                              // 64 data + 8 pad halves; 144B rows
#define GR   (2 * BM + BN)                   // 320 rows per buffer
#define BUFE (GR * ASTR)                     // halves per buffer

__global__ __launch_bounds__(256, 2)
void gemm_2p(const __half* __restrict__ Ah, const __half* __restrict__ Al,
             const __half* __restrict__ Bp,
             float* __restrict__ C, int M, int N, int K)
{
    extern __shared__ __half sm[];

    const int tid  = threadIdx.x;
    const int wid  = tid >> 5;
    const int lane = tid & 31;
    const int g    = lane >> 2;
    const int cq   = lane & 3;
    const int wm   = (wid & 3) * 32;
    const int wn   = (wid >> 2) * 32;
    const int bm   = blockIdx.y * BM;
    const int bn   = blockIdx.x * BN;

    float acc[2][4][4];
#pragma unroll
    for (int mt = 0; mt < 2; mt++)
#pragma unroll
        for (int nt = 0; nt < 4; nt++)
#pragma unroll
            for (int i = 0; i < 4; i++) acc[mt][nt][i] = 0.f;

    const int ntile = K / BK;

    auto load_tile = [&](int t, int buf) {
        const int k0 = t * BK;
        __half* s = sm + buf * BUFE;
#pragma unroll
        for (int i = 0; i < 10; i++) {
            int c = tid + i * 256;
            int r = c >> 3, col = (c & 7) * 8;
            const __half* src;
            if (r < BM)            src = Ah + (size_t)(bm + r) * K + k0 + col;
            else if (r < 2 * BM)   src = Al + (size_t)(bm + r - BM) * K + k0 + col;
            else                   src = Bp + (size_t)(bn + r - 2 * BM) * K + k0 + col;
            CP16(smemu32(s + r * ASTR + col), src);
        }
        asm volatile("cp.async.commit_group;" ::);
    };

    load_tile(0, 0);

    const int lr  = lane & 15;
    const int hb  = (lane >> 4) * 8;
    const int l8  = lane & 7;
    const int sel = lane >> 3;

    for (int t = 0; t < ntile; t++) {
        asm volatile("cp.async.wait_group 0;" ::);
        __syncthreads();
        if (t + 1 < ntile) load_tile(t + 1, (t + 1) & 1);

        const __half* s = sm + (t & 1) * BUFE;
#pragma unroll
        for (int kk = 0; kk < 4; kk++) {
            uint32_t ah2[2][4], al2[2][4], bh2[2][4];
#pragma unroll
            for (int mt = 0; mt < 2; mt++) {
                uint32_t addr = smemu32(s + (wm + mt * 16 + lr) * ASTR + kk * 16 + hb);
                LDSM4(ah2[mt][0], ah2[mt][1], ah2[mt][2], ah2[mt][3], addr);
                addr = smemu32(s + BM * ASTR + (wm + mt * 16 + lr) * ASTR + kk * 16 + hb);
                LDSM4(al2[mt][0], al2[mt][1], al2[mt][2], al2[mt][3], addr);
            }
#pragma unroll
            for (int np = 0; np < 2; np++) {
                const int brow = wn + np * 16 + ((sel >> 1) << 3) + l8;
                const int bcol = kk * 16 + (sel & 1) * 8;
                LDSM4(bh2[np][0], bh2[np][1], bh2[np][2], bh2[np][3],
                      smemu32(s + 2 * BM * ASTR + brow * ASTR + bcol));
            }
#pragma unroll
            for (int mt = 0; mt < 2; mt++)
#pragma unroll
                for (int np = 0; np < 2; np++) {
                    mma16816(acc[mt][2 * np],     ah2[mt], &bh2[np][0]);
                    mma16816(acc[mt][2 * np + 1], ah2[mt], &bh2[np][2]);
                }
#pragma unroll
            for (int mt = 0; mt < 2; mt++)
#pragma unroll
                for (int np = 0; np < 2; np++) {
                    mma16816(acc[mt][2 * np],     al2[mt], &bh2[np][0]);
                    mma16816(acc[mt][2 * np + 1], al2[mt], &bh2[np][2]);
                }
        }
    }

#pragma unroll
    for (int mt = 0; mt < 2; mt++)
#pragma unroll
        for (int nt = 0; nt < 4; nt++) {
            int row = bm + wm + mt * 16 + g;
            int col = bn + wn + nt * 8 + cq * 2;
            *(float2*)&C[(size_t)row * N + col]       = make_float2(acc[mt][nt][0], acc[mt][nt][1]);
            *(float2*)&C[(size_t)(row + 8) * N + col] = make_float2(acc[mt][nt][2], acc[mt][nt][3]);
        }
}

// ---------------------------------------------------------------------------
// RoPE + split to fp16 planes. 128-thread blocks, 4 rows (warps) per block.
// ---------------------------------------------------------------------------
__global__ __launch_bounds__(128)
void rope_split(const int* __restrict__ positions)
{
    const int row = blockIdx.x * 4 + (threadIdx.x >> 5);  // 0 .. S*(NH+NKV)-1
    const int s  = row / (NH_ + NKV_);
    const int hh = row % (NH_ + NKV_);
    const int i  = threadIdx.x & 31;

    const float pos = (float)positions[s];
    const float inv_freq = powf(10000.0f, -(float)i / 32.0f);
    const float ang = pos * inv_freq;
    float c, sn;
    sincosf(ang, &sn, &c);

    const float* src;
    __half *dh, *dl;
    if (hh < NH_) {
        src = &g_qkv[(size_t)s * QKV_N_ + hh * HD_];
        dh = &g_qh[(size_t)s * (NH_ * HD_) + hh * HD_];
        dl = &g_ql[(size_t)s * (NH_ * HD_) + hh * HD_];
    } else {
        const int kvh = hh - NH_;
        src = &g_qkv[(size_t)s * QKV_N_ + KOFF_ + kvh * HD_];
        dh = &g_kh[(size_t)s * (NKV_ * HD_) + kvh * HD_];
        dl = &g_kl[(size_t)s * (NKV_ * HD_) + kvh * HD_];
    }
    const float x1 = src[i];
    const float x2 = src[i + 32];
    const float r1 = x1 * c - x2 * sn;
    const float r2 = x2 * c + x1 * sn;
    __half h1 = __float2half_rn(r1);
    __half h2 = __float2half_rn(r2);
    dh[i]      = h1;
    dh[i + 32] = h2;
    dl[i]      = __float2half_rn(r1 - __half2float(h1));
    dl[i + 32] = __float2half_rn(r2 - __half2float(h2));
}

// ---------------------------------------------------------------------------
// Flash attention fp16: 128-query tile, 256 threads (8 warps x 16 rows).
// K/V staged via cp.async, double-buffered (2-stage pipeline), 16B chunks.
// Q 2-plane, K 2-plane (3-pass QK^T), P 2-plane, V single plane (2-pass PV).
// ---------------------------------------------------------------------------
#define VSTR 36                       // words per row (32 data + 4 pad) = 144B
#define KVROWS 192                    // K hi 64 + K lo 64 + V 64
#define STAGE_W (KVROWS * VSTR)       // words per K/V stage
#define FSMEM (2 * STAGE_W * 4)       // 55296 B dynamic

__global__ __launch_bounds__(256, 2)
void flash_attn(const float* __restrict__ sinks)
{
    extern __shared__ uint32_t SB[];  // 2 stages; Q staged into [0, 2*128*VSTR) first

    const int h   = blockIdx.y;
    const int qt  = (S_ / 128 - 1) - blockIdx.x;   // heavy tiles first
    const int q0  = qt * 128;
    const int kv  = h >> 3;
    const int tid = threadIdx.x;
    const int wid = tid >> 5;                      // 0..7
    const int lane = tid & 31;
    const int g   = lane >> 2;
    const int cq  = lane & 3;
    const float sink = sinks[h];

    // ---- stage Q tile (both planes) via cp.async ----
    {
        const int row = tid >> 1, e = tid & 1;
        const __half* qh = &g_qh[(size_t)(q0 + row) * (NH_ * HD_) + h * HD_ + e * 32];
        const __half* ql = &g_ql[(size_t)(q0 + row) * (NH_ * HD_) + h * HD_ + e * 32];
#pragma unroll
        for (int c = 0; c < 4; c++) {
            CP16(smemu32(SB + row * VSTR + e * 16 + c * 4), qh + c * 8);
            CP16(smemu32(SB + 128 * VSTR + row * VSTR + e * 16 + c * 4), ql + c * 8);
        }
        asm volatile("cp.async.commit_group;" ::);
        asm volatile("cp.async.wait_group 0;" ::);
    }
    __syncthreads();

    // ---- Q fragments in registers ----
    uint32_t qa[2][4][4];
    {
        const int r0 = (wid * 16 + g) * VSTR;
        const int r8 = r0 + 8 * VSTR;
#pragma unroll
        for (int p = 0; p < 2; p++) {
            const int base = p * 128 * VSTR;
#pragma unroll
            for (int kt = 0; kt < 4; kt++) {
                const int w0 = kt * 8 + cq;
                qa[p][kt][0] = SB[base + r0 + w0];
                qa[p][kt][1] = SB[base + r8 + w0];
                qa[p][kt][2] = SB[base + r0 + w0 + 4];
                qa[p][kt][3] = SB[base + r8 + w0 + 4];
            }
        }
    }
    __syncthreads();   // Q smem free for K/V double buffer

    // K/V stage loader: 6 cp.async per thread (K hi 2, K lo 2, V 2)
    auto stageKV = [&](int t, int buf) {
        uint32_t* base = SB + buf * STAGE_W;
        const int k0 = t * 64;
#pragma unroll
        for (int i = 0; i < 2; i++) {
            const int c = tid + i * 256;
            const int r = c >> 3, seg = c & 7;        // r: 0..63, seg: 16B chunk
            CP16(smemu32(base + r * VSTR + seg * 4),
                 &g_kh[(size_t)(k0 + r) * (NKV_ * HD_) + kv * HD_ + seg * 8]);
            CP16(smemu32(base + 64 * VSTR + r * VSTR + seg * 4),
                 &g_kl[(size_t)(k0 + r) * (NKV_ * HD_) + kv * HD_ + seg * 8]);
            CP16(smemu32(base + 128 * VSTR + r * VSTR + seg * 4),
                 &g_vt[((size_t)kv * HD_ + r) * S_ + k0 + seg * 8]);
        }
        asm volatile("cp.async.commit_group;" ::);
    };

    float oacc[8][4];
#pragma unroll
    for (int nt = 0; nt < 8; nt++)
#pragma unroll
        for (int i = 0; i < 4; i++) oacc[nt][i] = 0.f;
    float m0 = -INFINITY, m8 = -INFINITY;
    float l0 = 0.f, l8 = 0.f;

    const int row_g  = q0 + wid * 16 + g;
    const int row_g8 = row_g + 8;
    const int wrow_max = q0 + wid * 16 + 15;
    const int ntiles = (q0 + 128) >> 6;

    stageKV(0, 0);

    for (int t = 0; t < ntiles; t++) {
        const int k0 = t * 64;

        if (t + 1 < ntiles) {
            stageKV(t + 1, (t + 1) & 1);
            asm volatile("cp.async.wait_group 1;" ::);
        } else {
            asm volatile("cp.async.wait_group 0;" ::);
        }
        __syncthreads();

        const uint32_t* Ks0 = SB + (t & 1) * STAGE_W;
        const uint32_t* Ks1 = Ks0 + 64 * VSTR;
        const uint32_t* Vs  = Ks0 + 128 * VSTR;

        if (k0 <= wrow_max) {
            // ---- S = Q K^T (3-pass: qh*kh, qh*kl, ql*kh) ----
            float sacc[8][4];
#pragma unroll
            for (int nt = 0; nt < 8; nt++)
#pragma unroll
                for (int i = 0; i < 4; i++) sacc[nt][i] = 0.f;

#pragma unroll
            for (int kt = 0; kt < 4; kt++) {
                uint32_t kh[8][2], kl[8][2];
#pragma unroll
                for (int nt = 0; nt < 8; nt++) {
                    const int r0 = (nt * 8 + g) * VSTR + kt * 8 + cq;
                    kh[nt][0] = Ks0[r0]; kh[nt][1] = Ks0[r0 + 4];
                    kl[nt][0] = Ks1[r0]; kl[nt][1] = Ks1[r0 + 4];
                }
#pragma unroll
                for (int nt = 0; nt < 8; nt++) mma16816(sacc[nt], qa[0][kt], kh[nt]);
#pragma unroll
                for (int nt = 0; nt < 8; nt++) mma16816(sacc[nt], qa[0][kt], kl[nt]);
#pragma unroll
                for (int nt = 0; nt < 8; nt++) mma16816(sacc[nt], qa[1][kt], kh[nt]);
            }

            // ---- scale + causal mask (diagonal tiles only) ----
            const bool need_mask = (k0 + 63 > row_g);
#pragma unroll
            for (int nt = 0; nt < 8; nt++) {
                const int c0 = k0 + nt * 8 + 2 * cq;
#pragma unroll
                for (int i = 0; i < 4; i++) sacc[nt][i] *= SCALE_;
                if (need_mask) {
                    if (c0     > row_g)  sacc[nt][0] = -INFINITY;
                    if (c0 + 1 > row_g)  sacc[nt][1] = -INFINITY;
                    if (c0     > row_g8) sacc[nt][2] = -INFINITY;
                    if (c0 + 1 > row_g8) sacc[nt][3] = -INFINITY;
                }
            }

            // ---- online softmax update ----
            float tm0 = -INFINITY, tm8 = -INFINITY;
#pragma unroll
            for (int nt = 0; nt < 8; nt++) {
                tm0 = fmaxf(tm0, fmaxf(sacc[nt][0], sacc[nt][1]));
                tm8 = fmaxf(tm8, fmaxf(sacc[nt][2], sacc[nt][3]));
            }
            tm0 = fmaxf(tm0, __shfl_xor_sync(0xffffffffu, tm0, 1));
            tm0 = fmaxf(tm0, __shfl_xor_sync(0xffffffffu, tm0, 2));
            tm8 = fmaxf(tm8, __shfl_xor_sync(0xffffffffu, tm8, 1));
            tm8 = fmaxf(tm8, __shfl_xor_sync(0xffffffffu, tm8, 2));

            const float m0n = fmaxf(m0, tm0);
            const float m8n = fmaxf(m8, tm8);
            const float a0 = __expf(m0 - m0n);
            const float a8 = __expf(m8 - m8n);
            m0 = m0n; m8 = m8n;
            l0 *= a0; l8 *= a8;
#pragma unroll
            for (int nt = 0; nt < 8; nt++) {
                oacc[nt][0] *= a0; oacc[nt][1] *= a0;
                oacc[nt][2] *= a8; oacc[nt][3] *= a8;
            }

#pragma unroll
            for (int nt = 0; nt < 8; nt++) {
                float p0 = (sacc[nt][0] == -INFINITY) ? 0.f : __expf(sacc[nt][0] - m0);
                float p1 = (sacc[nt][1] == -INFINITY) ? 0.f : __expf(sacc[nt][1] - m0);
                float p2 = (sacc[nt][2] == -INFINITY) ? 0.f : __expf(sacc[nt][2] - m8);
                float p3 = (sacc[nt][3] == -INFINITY) ? 0.f : __expf(sacc[nt][3] - m8);
                sacc[nt][0] = p0; sacc[nt][1] = p1; sacc[nt][2] = p2; sacc[nt][3] = p3;
                l0 += p0 + p1;
                l8 += p2 + p3;
            }

            // ---- O += P V (P 2-plane, V single: 2-pass) ----
#pragma unroll
            for (int kt = 0; kt < 4; kt++) {
                uint32_t pah[4], pal[4];
                split2h(sacc[2 * kt][0],     sacc[2 * kt][1],     pah[0], pal[0]);
                split2h(sacc[2 * kt][2],     sacc[2 * kt][3],     pah[1], pal[1]);
                split2h(sacc[2 * kt + 1][0], sacc[2 * kt + 1][1], pah[2], pal[2]);
                split2h(sacc[2 * kt + 1][2], sacc[2 * kt + 1][3], pah[3], pal[3]);
                uint32_t vh[8][2];
#pragma unroll
                for (int nt = 0; nt < 8; nt++) {
                    const int r0 = (nt * 8 + g) * VSTR + kt * 8 + cq;
                    vh[nt][0] = Vs[r0]; vh[nt][1] = Vs[r0 + 4];
                }
#pragma unroll
                for (int nt = 0; nt < 8; nt++) mma16816(oacc[nt], pah, vh[nt]);
#pragma unroll
                for (int nt = 0; nt < 8; nt++) mma16816(oacc[nt], pal, vh[nt]);
            }
        }
        __syncthreads();   // release buffer t&1 before stage t+2 overwrites it
    }

    // ---- finalize with sink; write fp16 hi/lo planes ----
    {
        const float m0n = fmaxf(m0, sink);
        const float m8n = fmaxf(m8, sink);
        const float a0 = __expf(m0 - m0n);
        const float a8 = __expf(m8 - m8n);
        l0 *= a0; l8 *= a8;
        l0 += __shfl_xor_sync(0xffffffffu, l0, 1);
        l0 += __shfl_xor_sync(0xffffffffu, l0, 2);
        l8 += __shfl_xor_sync(0xffffffffu, l8, 1);
        l8 += __shfl_xor_sync(0xffffffffu, l8, 2);
        const float inv0 = a0 / (l0 + __expf(sink - m0n));
        const float inv8 = a8 / (l8 + __expf(sink - m8n));
#pragma unroll
        for (int nt = 0; nt < 8; nt++) {
            const int col = h * HD_ + nt * 8 + 2 * cq;
            uint32_t hw, lw;
            split2h(oacc[nt][0] * inv0, oacc[nt][1] * inv0, hw, lw);
            *(uint32_t*)&g_ah[(size_t)row_g * ATTN_N_ + col] = hw;
            *(uint32_t*)&g_al[(size_t)row_g * ATTN_N_ + col] = lw;
            split2h(oacc[nt][2] * inv8, oacc[nt][3] * inv8, hw, lw);
            *(uint32_t*)&g_ah[(size_t)row_g8 * ATTN_N_ + col] = hw;
            *(uint32_t*)&g_al[(size_t)row_g8 * ATTN_N_ + col] = lw;
        }
    }
}

// ---------------------------------------------------------------------------
// Launch
// ---------------------------------------------------------------------------
extern "C" void kernel_launch(void* const* d_in, const int* in_sizes, int n_in,
                              void* d_out, int out_size)
{
    const int*   positions = (const int*)d_in[0];
    const float* hidden    = (const float*)d_in[1];
    const float* qkv_w     = (const float*)d_in[2];
    const float* o_w       = (const float*)d_in[3];
    const float* sinks     = (const float*)d_in[4];
    float*       out       = (float*)d_out;

    const int smem = 2 * BUFE * (int)sizeof(__half);   // 92160 B

    static bool attr_done = false;
    if (!attr_done) {
        cudaFuncSetAttribute(gemm_2p, cudaFuncAttributeMaxDynamicSharedMemorySize, smem);
        cudaFuncSetAttribute(flash_attn, cudaFuncAttributeMaxDynamicSharedMemorySize, FSMEM);
        attr_done = true;
    }

    void *p;
    cudaGetSymbolAddress(&p, g_qkv);  float* qkv = (float*)p;
    cudaGetSymbolAddress(&p, g_wq);   __half* wq = (__half*)p;
    cudaGetSymbolAddress(&p, g_wo);   __half* wo = (__half*)p;
    cudaGetSymbolAddress(&p, g_xh);   __half* xh = (__half*)p;
    cudaGetSymbolAddress(&p, g_xl);   __half* xl = (__half*)p;
    cudaGetSymbolAddress(&p, g_ah);   __half* ah = (__half*)p;
    cudaGetSymbolAddress(&p, g_al);   __half* al = (__half*)p;

    // 0) pre-convert: weights single fp16 plane, hidden 2-plane fp16
    cvt_f16<<<(QKV_N_ * H_) / 1024, 256>>>(qkv_w, wq, QKV_N_ * H_);
    cvt_f16<<<(H_ * ATTN_N_) / 1024, 256>>>(o_w, wo, H_ * ATTN_N_);
    split_f16<<<(S_ * H_) / 1024, 256>>>(hidden, xh, xl, S_ * H_);

    // 1) QKV projection: [1024,2880] @ [5120,2880]^T -> g_qkv fp32
    gemm_2p<<<dim3(QKV_N_ / BN, S_ / BM), 256, smem>>>(xh, xl, wq, qkv, S_, QKV_N_, H_);

    // 2) RoPE + split Q/K; transpose + convert V
    rope_split<<<S_ * (NH_ + NKV_) / 4, 128>>>(positions);
    vcvt_t<<<dim3(S_ / 32, NKV_), 256>>>();

    // 3) Flash attention -> attn planes (128-query tiles, cp.async pipeline)
    flash_attn<<<dim3(S_ / 128, NH_), 256, FSMEM>>>(sinks);

    // 4) O projection: attn planes @ o_w plane -> out fp32
    gemm_2p<<<dim3(H_ / BN, S_ / BM), 256, smem>>>(ah, al, wo, out, S_, H_, ATTN_N_);
}